// round 6
// baseline (speedup 1.0000x reference)
#include <cuda_runtime.h>
#include <cuda_bf16.h>
#include <cstdint>
#include <math.h>

#define NL 8
#define NE 8
#define ND 256
#define NB 16384
#define TM 128
#define NTH 512

// ---------------- helpers ----------------
__device__ __forceinline__ uint32_t smem_to_u32(const void* p) {
    uint32_t a;
    asm("{ .reg .u64 t; cvta.to.shared.u64 t, %1; cvt.u32.u64 %0, t; }" : "=r"(a) : "l"(p));
    return a;
}
__device__ __forceinline__ uint32_t packhi(float a, float b) {
    __nv_bfloat162 t;
    t.x = __float2bfloat16(a);
    t.y = __float2bfloat16(b);
    return *(uint32_t*)&t;
}
__device__ __forceinline__ uint32_t packlo(float a, float b) {
    __nv_bfloat162 t;
    t.x = __float2bfloat16(a - __bfloat162float(__float2bfloat16(a)));
    t.y = __float2bfloat16(b - __bfloat162float(__float2bfloat16(b)));
    return *(uint32_t*)&t;
}

#define MMA(c, ax, ay, az, aw, b0, b1) \
    asm volatile("mma.sync.aligned.m16n8k16.row.col.f32.bf16.bf16.f32 " \
        "{%0,%1,%2,%3},{%4,%5,%6,%7},{%8,%9},{%0,%1,%2,%3};" \
        : "+f"((c)[0]), "+f"((c)[1]), "+f"((c)[2]), "+f"((c)[3]) \
        : "r"(ax), "r"(ay), "r"(az), "r"(aw), "r"(b0), "r"(b1))

#define CP_COMMIT asm volatile("cp.async.commit_group;" ::: "memory")
#define CP_WAIT(n) asm volatile("cp.async.wait_group %0;" :: "n"(n) : "memory")

__device__ __forceinline__ void cpya(uint32_t dst, const unsigned char* src, int bytes, int tid) {
    for (int i = tid * 16; i < bytes; i += NTH * 16)
        asm volatile("cp.async.cg.shared.global [%0], [%1], 16;" :: "r"(dst + i), "l"(src + i));
}

// ---------------- global weight images ----------------
// per (l,e): W1hi 32768 | W1lo 32768 | W2i(interleaved) 8192 | W3i(interleaved) 32768
#define PER_LE 106496
#define B3OFF (64 * PER_LE)
__device__ __align__(16) unsigned char g_w[B3OFF + 8 * 8192];

__global__ void prep_kernel(const float* __restrict__ W1, const float* __restrict__ W2,
                            const float* __restrict__ W3, const float* __restrict__ b3) {
    const int le = blockIdx.x;
    const int t = threadIdx.x;
    unsigned char* base = g_w + (size_t)le * PER_LE;

    const float* W1p = W1 + (size_t)le * 16384;   // [64][256]
    for (int idx = t; idx < 4096; idx += 256) {
        int kt = idx >> 8, nt = (idx >> 5) & 7, ln = idx & 31;
        int n = nt * 8 + ln / 4, k = kt * 16 + (ln % 4) * 2;
        float f00 = W1p[n * 256 + k], f01 = W1p[n * 256 + k + 1];
        float f10 = W1p[n * 256 + k + 8], f11 = W1p[n * 256 + k + 9];
        *(uint2*)(base + idx * 8) = make_uint2(packhi(f00, f01), packhi(f10, f11));
        *(uint2*)(base + 32768 + idx * 8) = make_uint2(packlo(f00, f01), packlo(f10, f11));
    }
    const float* W2p = W2 + (size_t)le * 2048;    // [32][64] -> interleaved {hi,lo} uint4
    for (int idx = t; idx < 512; idx += 256) {
        int kt = idx >> 7, nt = (idx >> 5) & 3, ln = idx & 31;
        int n = nt * 8 + ln / 4, k = kt * 16 + (ln % 4) * 2;
        float f00 = W2p[n * 64 + k], f01 = W2p[n * 64 + k + 1];
        float f10 = W2p[n * 64 + k + 8], f11 = W2p[n * 64 + k + 9];
        *(uint4*)(base + 65536 + idx * 16) = make_uint4(packhi(f00, f01), packhi(f10, f11),
                                                        packlo(f00, f01), packlo(f10, f11));
    }
    const float* W3p = W3 + (size_t)le * 8192;    // [256][32] -> interleaved {hi,lo} uint4
    for (int idx = t; idx < 2048; idx += 256) {
        int kt = idx >> 10, nt = (idx >> 5) & 31, ln = idx & 31;
        int n = nt * 8 + ln / 4, k = kt * 16 + (ln % 4) * 2;
        float f00 = W3p[n * 32 + k], f01 = W3p[n * 32 + k + 1];
        float f10 = W3p[n * 32 + k + 8], f11 = W3p[n * 32 + k + 9];
        *(uint4*)(base + 73728 + idx * 16) = make_uint4(packhi(f00, f01), packhi(f10, f11),
                                                        packlo(f00, f01), packlo(f10, f11));
    }
    if ((le & 7) == 0) {
        int l = le >> 3;
        const float* b3p = b3 + (size_t)l * 2048;  // [8][256]
        unsigned char* bb = g_w + B3OFF + (size_t)l * 8192;
        for (int idx = t; idx < 1024; idx += 256) {
            int nt = idx >> 5, ln = idx & 31;
            int n = nt * 8 + ln / 4, e0 = (ln % 4) * 2;
            float v0 = b3p[e0 * 256 + n], v1 = b3p[(e0 + 1) * 256 + n];
            *(uint32_t*)(bb + idx * 4) = packhi(v0, v1);
            *(uint32_t*)(bb + 4096 + idx * 4) = packlo(v0, v1);
        }
    }
}

// ---------------- smem layout (bytes) ----------------
#define XFRAG 0          // 131072 (hi kt0-15, lo kt16-31)
#define BUFP  131072     // 32768 : W1hi -> h1 frags
#define BUFQ  163840     // 32768 : W1lo -> W3i
#define W2F   196608     // 8192 interleaved
#define H2F   204800     // 16384
#define WFA   221184     // 4096
#define WSOFT 225280     // 4096
#define B1S   229376     // 256
#define B2S   229632     // 128
#define SMEM_BYTES 229760
#define XLO 65536

__global__ void __launch_bounds__(NTH, 1)
moe_mma_kernel(const float* __restrict__ src,
               const float* __restrict__ b1, const float* __restrict__ b2,
               const float* __restrict__ masks, float* __restrict__ out)
{
    extern __shared__ char smem[];
    const uint32_t sbase = smem_to_u32(smem);
    const int tid = threadIdx.x;
    const int w = tid >> 5;
    const int ln = tid & 31;
    const int wm4 = w & 3;       // rowblock-pair (G1/G3)
    const int nq = w >> 2;       // n-quarter (G1/G3)
    const int rb = w >> 1;       // rowblock (G2)
    const int nhf = w & 1;       // n-half (G2)
    const int rowbase = blockIdx.x * TM;

    float* b1s = (float*)(smem + B1S);
    float* b2s = (float*)(smem + B2S);
    float* wsoft = (float*)(smem + WSOFT);
    uint32_t* xfrag = (uint32_t*)(smem + XFRAG);

    // prologue: preload W1hi_0, W1lo_0, W2i_0
    cpya(sbase + BUFP, g_w, 32768, tid);
    cpya(sbase + BUFQ, g_w + 32768, 32768, tid);
    cpya(sbase + W2F, g_w + 65536, 8192, tid);
    CP_COMMIT;

    // initial X -> A-fragment image (4 threads per row)
    {
        const int r = tid >> 2;
        const int q4 = tid & 3;
        const float* sp = src + (size_t)(rowbase + r) * ND;
        const int rhalf = (r & 15) >> 3;
        #pragma unroll 4
        for (int p = 32 * q4; p < 32 * q4 + 32; p++) {
            float f0 = sp[2 * p], f1 = sp[2 * p + 1];
            int kt = p >> 3;
            int lane = 4 * (r & 7) + (p & 3);
            int khalf = (p & 7) >> 2;
            int reg = 2 * khalf + rhalf;
            int slot = ((kt * 8 + (r >> 4)) * 32 + lane) * 4 + reg;
            xfrag[slot] = packhi(f0, f1);
            xfrag[slot + (XLO >> 2)] = packlo(f0, f1);
        }
    }

    float xacc[2][8][4];

    for (int l = 0; l < NL; l++) {
        if (tid < TM) {
            const int r = tid;
            const float* mp = masks + ((size_t)l * NB + rowbase + r) * NE;
            float m[8], mx = -1e30f;
            #pragma unroll
            for (int e = 0; e < 8; e++) { m[e] = mp[e]; mx = fmaxf(mx, m[e]); }
            float s = 0.f;
            #pragma unroll
            for (int e = 0; e < 8; e++) { m[e] = expf(m[e] - mx); s += m[e]; }
            s = 1.f / s;
            #pragma unroll
            for (int e = 0; e < 8; e++) { m[e] *= s; wsoft[r * 8 + e] = m[e]; }
            uint32_t* wfa = (uint32_t*)(smem + WFA);
            const int rhalf = (r & 15) >> 3;
            #pragma unroll
            for (int q = 0; q < 4; q++) {
                int ub = (((r >> 4) * 32) + 4 * (r & 7) + q) * 4;
                wfa[ub + rhalf] = packhi(m[2 * q], m[2 * q + 1]);
                wfa[ub + 2 + rhalf] = packlo(m[2 * q], m[2 * q + 1]);
            }
        }
        #pragma unroll
        for (int i = 0; i < 2; i++)
            #pragma unroll
            for (int j = 0; j < 8; j++)
                #pragma unroll
                for (int q = 0; q < 4; q++) xacc[i][j][q] = 0.f;

        for (int e = 0; e < NE; e++) {
            const int idx = l * 8 + e;
            const unsigned char* wp = g_w + (size_t)idx * PER_LE;
            const unsigned char* wn = g_w + (size_t)(idx < 63 ? idx + 1 : 63) * PER_LE;

            CP_WAIT(0);
            __syncthreads();           // P=W1hi, Q=W1lo, W2F ready; xfrag/wfa visible
            if (tid < 64) b1s[tid] = b1[(size_t)idx * 64 + tid];
            else if (tid < 96) b2s[tid - 64] = b2[(size_t)idx * 32 + tid - 64];

            // ---- G1: all 3 products in one k-loop ----
            float c1[2][2][4];
            #pragma unroll
            for (int i = 0; i < 2; i++)
                #pragma unroll
                for (int j = 0; j < 2; j++)
                    #pragma unroll
                    for (int q = 0; q < 4; q++) c1[i][j][q] = 0.f;
            {
                const char* Pp = smem + BUFP;
                const char* Qp = smem + BUFQ;
                #pragma unroll 4
                for (int kt = 0; kt < 16; kt++) {
                    const char* xb = smem + XFRAG + ((kt * 8 + 2 * wm4) * 32 + ln) * 16;
                    uint4 a0h = *(const uint4*)xb;
                    uint4 a1h = *(const uint4*)(xb + 512);
                    uint4 a0l = *(const uint4*)(xb + XLO);
                    uint4 a1l = *(const uint4*)(xb + XLO + 512);
                    #pragma unroll
                    for (int nt = 0; nt < 2; nt++) {
                        int gnt = 2 * nq + nt;
                        uint2 bh = *(const uint2*)(Pp + ((kt * 8 + gnt) * 32 + ln) * 8);
                        uint2 bl = *(const uint2*)(Qp + ((kt * 8 + gnt) * 32 + ln) * 8);
                        MMA(c1[0][nt], a0h.x, a0h.y, a0h.z, a0h.w, bh.x, bh.y);
                        MMA(c1[1][nt], a1h.x, a1h.y, a1h.z, a1h.w, bh.x, bh.y);
                        MMA(c1[0][nt], a0l.x, a0l.y, a0l.z, a0l.w, bh.x, bh.y);
                        MMA(c1[1][nt], a1l.x, a1l.y, a1l.z, a1l.w, bh.x, bh.y);
                        MMA(c1[0][nt], a0h.x, a0h.y, a0h.z, a0h.w, bl.x, bl.y);
                        MMA(c1[1][nt], a1h.x, a1h.y, a1h.z, a1h.w, bl.x, bl.y);
                    }
                }
            }
            __syncthreads();           // P/Q readers done; b1s visible

            // ---- D1 epilogue -> h1 frags into P; kick W3 -> Q ----
            {
                char* Pp = smem + BUFP;
                #pragma unroll
                for (int rt = 0; rt < 2; rt++) {
                    int rtg = 2 * wm4 + rt;
                    float v[2][4];
                    #pragma unroll
                    for (int nt = 0; nt < 2; nt++) {
                        int gc = 16 * nq + nt * 8 + (ln & 3) * 2;
                        float bb0 = b1s[gc], bb1 = b1s[gc + 1];
                        float* c = c1[rt][nt];
                        v[nt][0] = fmaxf(c[0] + bb0, 0.f);
                        v[nt][1] = fmaxf(c[1] + bb1, 0.f);
                        v[nt][2] = fmaxf(c[2] + bb0, 0.f);
                        v[nt][3] = fmaxf(c[3] + bb1, 0.f);
                    }
                    uint4 hi = make_uint4(packhi(v[0][0], v[0][1]), packhi(v[0][2], v[0][3]),
                                          packhi(v[1][0], v[1][1]), packhi(v[1][2], v[1][3]));
                    uint4 lo = make_uint4(packlo(v[0][0], v[0][1]), packlo(v[0][2], v[0][3]),
                                          packlo(v[1][0], v[1][1]), packlo(v[1][2], v[1][3]));
                    *(uint4*)(Pp + ((nq * 8 + rtg) * 32 + ln) * 16) = hi;
                    *(uint4*)(Pp + (((nq + 4) * 8 + rtg) * 32 + ln) * 16) = lo;
                }
            }
            cpya(sbase + BUFQ, wp + 73728, 32768, tid);   // W3i -> Q
            CP_COMMIT;
            __syncthreads();           // h1 visible

            // ---- G2: h1 (P) x W2 (interleaved) ----
            float c2[2][4];
            #pragma unroll
            for (int j = 0; j < 2; j++)
                #pragma unroll
                for (int q = 0; q < 4; q++) c2[j][q] = 0.f;
            {
                const char* Pp = smem + BUFP;
                #pragma unroll
                for (int kt = 0; kt < 4; kt++) {
                    uint4 ah = *(const uint4*)(Pp + ((kt * 8 + rb) * 32 + ln) * 16);
                    uint4 al = *(const uint4*)(Pp + (((kt + 4) * 8 + rb) * 32 + ln) * 16);
                    #pragma unroll
                    for (int nt = 0; nt < 2; nt++) {
                        int ntg = 2 * nhf + nt;
                        uint4 b = *(const uint4*)(smem + W2F + ((kt * 4 + ntg) * 32 + ln) * 16);
                        MMA(c2[nt], ah.x, ah.y, ah.z, ah.w, b.x, b.y);
                        MMA(c2[nt], al.x, al.y, al.z, al.w, b.x, b.y);
                        MMA(c2[nt], ah.x, ah.y, ah.z, ah.w, b.z, b.w);
                    }
                }
            }
            // ---- D2 epilogue -> h2 frags into H2F ----
            {
                float wg0 = wsoft[(16 * rb + ln / 4) * 8 + e];
                float wg1 = wsoft[(16 * rb + 8 + ln / 4) * 8 + e];
                float v[2][4];
                #pragma unroll
                for (int nt = 0; nt < 2; nt++) {
                    int gc = 16 * nhf + nt * 8 + (ln & 3) * 2;
                    float bb0 = b2s[gc], bb1 = b2s[gc + 1];
                    float* c = c2[nt];
                    v[nt][0] = fmaxf(c[0] + bb0, 0.f) * wg0;
                    v[nt][1] = fmaxf(c[1] + bb1, 0.f) * wg0;
                    v[nt][2] = fmaxf(c[2] + bb0, 0.f) * wg1;
                    v[nt][3] = fmaxf(c[3] + bb1, 0.f) * wg1;
                }
                uint4 hi = make_uint4(packhi(v[0][0], v[0][1]), packhi(v[0][2], v[0][3]),
                                      packhi(v[1][0], v[1][1]), packhi(v[1][2], v[1][3]));
                uint4 lo = make_uint4(packlo(v[0][0], v[0][1]), packlo(v[0][2], v[0][3]),
                                      packlo(v[1][0], v[1][1]), packlo(v[1][2], v[1][3]));
                *(uint4*)(smem + H2F + ((nhf * 8 + rb) * 32 + ln) * 16) = hi;
                *(uint4*)(smem + H2F + (((nhf + 2) * 8 + rb) * 32 + ln) * 16) = lo;
            }
            CP_WAIT(0);                // W3 (Q) landed (per-thread)
            __syncthreads();           // h2 + Q visible; P(h1), W2F dead
            cpya(sbase + BUFP, wn, 32768, tid);           // next W1hi -> P
            cpya(sbase + W2F, wn + 65536, 8192, tid);     // next W2i
            CP_COMMIT;

            // ---- G3: h2 x W3 (B loaded once; A in regs) ----
            {
                const char* Qp = smem + BUFQ;
                const unsigned char* gb3 = g_w + B3OFF + (size_t)l * 8192;
                uint4 A[2][4];   // [rt][ah0,ah1,al0,al1]
                #pragma unroll
                for (int rt = 0; rt < 2; rt++) {
                    int rtg = 2 * wm4 + rt;
                    A[rt][0] = *(const uint4*)(smem + H2F + ((0 * 8 + rtg) * 32 + ln) * 16);
                    A[rt][1] = *(const uint4*)(smem + H2F + ((1 * 8 + rtg) * 32 + ln) * 16);
                    A[rt][2] = *(const uint4*)(smem + H2F + ((2 * 8 + rtg) * 32 + ln) * 16);
                    A[rt][3] = *(const uint4*)(smem + H2F + ((3 * 8 + rtg) * 32 + ln) * 16);
                }
                uint4 wf0 = *(const uint4*)(smem + WFA + ((2 * wm4) * 32 + ln) * 16);
                uint4 wf1 = *(const uint4*)(smem + WFA + ((2 * wm4 + 1) * 32 + ln) * 16);
                #pragma unroll
                for (int nt = 0; nt < 8; nt++) {
                    int gnt = 8 * nq + nt;
                    uint4 b0 = *(const uint4*)(Qp + ((0 * 32 + gnt) * 32 + ln) * 16);
                    uint4 b1v = *(const uint4*)(Qp + ((32 + gnt) * 32 + ln) * 16);
                    #pragma unroll
                    for (int rt = 0; rt < 2; rt++) {
                        float* cc = xacc[rt][nt];
                        MMA(cc, A[rt][0].x, A[rt][0].y, A[rt][0].z, A[rt][0].w, b0.x, b0.y);
                        MMA(cc, A[rt][1].x, A[rt][1].y, A[rt][1].z, A[rt][1].w, b1v.x, b1v.y);
                        MMA(cc, A[rt][2].x, A[rt][2].y, A[rt][2].z, A[rt][2].w, b0.x, b0.y);
                        MMA(cc, A[rt][3].x, A[rt][3].y, A[rt][3].z, A[rt][3].w, b1v.x, b1v.y);
                        MMA(cc, A[rt][0].x, A[rt][0].y, A[rt][0].z, A[rt][0].w, b0.z, b0.w);
                        MMA(cc, A[rt][1].x, A[rt][1].y, A[rt][1].z, A[rt][1].w, b1v.z, b1v.w);
                    }
                    if (e == 0) {
                        uint32_t p3h = *(const uint32_t*)(gb3 + (gnt * 32 + ln) * 4);
                        uint32_t p3l = *(const uint32_t*)(gb3 + 4096 + (gnt * 32 + ln) * 4);
                        MMA(xacc[0][nt], wf0.x, wf0.y, wf0.z, wf0.w, p3h, p3h);
                        MMA(xacc[0][nt], wf0.x, wf0.y, 0u, 0u, p3l, 0u);
                        MMA(xacc[1][nt], wf1.x, wf1.y, wf1.z, wf1.w, p3h, p3h);
                        MMA(xacc[1][nt], wf1.x, wf1.y, 0u, 0u, p3l, 0u);
                    }
                }
            }
            __syncthreads();           // Q readers done
            cpya(sbase + BUFQ, wn + 32768, 32768, tid);   // next W1lo -> Q
            CP_COMMIT;
        } // experts

        // ---- layer end: xacc -> xfrag or out ----
        if (l == NL - 1) {
            #pragma unroll
            for (int rt = 0; rt < 2; rt++) {
                int r0 = 32 * wm4 + rt * 16 + ln / 4;
                #pragma unroll
                for (int nt = 0; nt < 8; nt++) {
                    int col = 64 * nq + nt * 8 + (ln & 3) * 2;
                    float* cc = xacc[rt][nt];
                    *(float2*)(out + (size_t)(rowbase + r0) * ND + col) = make_float2(cc[0], cc[1]);
                    *(float2*)(out + (size_t)(rowbase + r0 + 8) * ND + col) = make_float2(cc[2], cc[3]);
                }
            }
        } else {
            #pragma unroll
            for (int rt = 0; rt < 2; rt++) {
                int rtg = 2 * wm4 + rt;
                #pragma unroll
                for (int nt = 0; nt < 8; nt++) {
                    int kt = 4 * nq + (nt >> 1);
                    float* cc = xacc[rt][nt];
                    int sb = ((kt * 8 + rtg) * 32 + ln) * 4 + 2 * (nt & 1);
                    xfrag[sb] = packhi(cc[0], cc[1]);
                    xfrag[sb + 1] = packhi(cc[2], cc[3]);
                    xfrag[sb + (XLO >> 2)] = packlo(cc[0], cc[1]);
                    xfrag[sb + (XLO >> 2) + 1] = packlo(cc[2], cc[3]);
                }
            }
        }
    } // layers
    CP_WAIT(0);
}

extern "C" void kernel_launch(void* const* d_in, const int* in_sizes, int n_in,
                              void* d_out, int out_size)
{
    const float* src   = (const float*)d_in[0];
    const float* W1    = (const float*)d_in[1];
    const float* b1    = (const float*)d_in[2];
    const float* W2    = (const float*)d_in[3];
    const float* b2    = (const float*)d_in[4];
    const float* W3    = (const float*)d_in[5];
    const float* b3    = (const float*)d_in[6];
    const float* masks = (const float*)d_in[7];
    float* out = (float*)d_out;
    (void)in_sizes; (void)n_in; (void)out_size;

    prep_kernel<<<64, 256>>>(W1, W2, W3, b3);
    cudaFuncSetAttribute(moe_mma_kernel,
                         cudaFuncAttributeMaxDynamicSharedMemorySize, SMEM_BYTES);
    moe_mma_kernel<<<NB / TM, NTH, SMEM_BYTES>>>(src, b1, b2, masks, out);
}

// round 7
// speedup vs baseline: 1.3418x; 1.3418x over previous
#include <cuda_runtime.h>
#include <cuda_bf16.h>
#include <cstdint>
#include <math.h>

#define NL 8
#define NE 8
#define ND 256
#define NB 16384
#define TM 128
#define NTH 512

// ---------------- helpers ----------------
__device__ __forceinline__ uint32_t smem_to_u32(const void* p) {
    uint32_t a;
    asm("{ .reg .u64 t; cvta.to.shared.u64 t, %1; cvt.u32.u64 %0, t; }" : "=r"(a) : "l"(p));
    return a;
}
__device__ __forceinline__ uint32_t packhi(float a, float b) {
    __nv_bfloat162 t;
    t.x = __float2bfloat16(a);
    t.y = __float2bfloat16(b);
    return *(uint32_t*)&t;
}
__device__ __forceinline__ uint32_t packlo(float a, float b) {
    __nv_bfloat162 t;
    t.x = __float2bfloat16(a - __bfloat162float(__float2bfloat16(a)));
    t.y = __float2bfloat16(b - __bfloat162float(__float2bfloat16(b)));
    return *(uint32_t*)&t;
}

#define MMA(c, ax, ay, az, aw, b0, b1) \
    asm volatile("mma.sync.aligned.m16n8k16.row.col.f32.bf16.bf16.f32 " \
        "{%0,%1,%2,%3},{%4,%5,%6,%7},{%8,%9},{%0,%1,%2,%3};" \
        : "+f"((c)[0]), "+f"((c)[1]), "+f"((c)[2]), "+f"((c)[3]) \
        : "r"(ax), "r"(ay), "r"(az), "r"(aw), "r"(b0), "r"(b1))

#define CP_COMMIT asm volatile("cp.async.commit_group;" ::: "memory")
#define CP_WAIT(n) asm volatile("cp.async.wait_group %0;" :: "n"(n) : "memory")

__device__ __forceinline__ void cpya(uint32_t dst, const unsigned char* src, int bytes, int tid) {
    for (int i = tid * 16; i < bytes; i += NTH * 16)
        asm volatile("cp.async.cg.shared.global [%0], [%1], 16;" :: "r"(dst + i), "l"(src + i));
}

// ---------------- global weight images ----------------
// per (l,e): W1hi 32768 | W1lo 32768 | W2i(interleaved) 8192 | W3i(interleaved) 32768
#define PER_LE 106496
#define B3OFF (64 * PER_LE)
__device__ __align__(16) unsigned char g_w[B3OFF + 8 * 8192];

__global__ void prep_kernel(const float* __restrict__ W1, const float* __restrict__ W2,
                            const float* __restrict__ W3, const float* __restrict__ b3) {
    const int le = blockIdx.x;
    const int t = threadIdx.x;
    unsigned char* base = g_w + (size_t)le * PER_LE;

    const float* W1p = W1 + (size_t)le * 16384;   // [64][256]
    for (int idx = t; idx < 4096; idx += 256) {
        int kt = idx >> 8, nt = (idx >> 5) & 7, ln = idx & 31;
        int n = nt * 8 + ln / 4, k = kt * 16 + (ln % 4) * 2;
        float f00 = W1p[n * 256 + k], f01 = W1p[n * 256 + k + 1];
        float f10 = W1p[n * 256 + k + 8], f11 = W1p[n * 256 + k + 9];
        *(uint2*)(base + idx * 8) = make_uint2(packhi(f00, f01), packhi(f10, f11));
        *(uint2*)(base + 32768 + idx * 8) = make_uint2(packlo(f00, f01), packlo(f10, f11));
    }
    const float* W2p = W2 + (size_t)le * 2048;    // [32][64] -> interleaved {hi,lo} uint4
    for (int idx = t; idx < 512; idx += 256) {
        int kt = idx >> 7, nt = (idx >> 5) & 3, ln = idx & 31;
        int n = nt * 8 + ln / 4, k = kt * 16 + (ln % 4) * 2;
        float f00 = W2p[n * 64 + k], f01 = W2p[n * 64 + k + 1];
        float f10 = W2p[n * 64 + k + 8], f11 = W2p[n * 64 + k + 9];
        *(uint4*)(base + 65536 + idx * 16) = make_uint4(packhi(f00, f01), packhi(f10, f11),
                                                        packlo(f00, f01), packlo(f10, f11));
    }
    const float* W3p = W3 + (size_t)le * 8192;    // [256][32] -> interleaved {hi,lo} uint4
    for (int idx = t; idx < 2048; idx += 256) {
        int kt = idx >> 10, nt = (idx >> 5) & 31, ln = idx & 31;
        int n = nt * 8 + ln / 4, k = kt * 16 + (ln % 4) * 2;
        float f00 = W3p[n * 32 + k], f01 = W3p[n * 32 + k + 1];
        float f10 = W3p[n * 32 + k + 8], f11 = W3p[n * 32 + k + 9];
        *(uint4*)(base + 73728 + idx * 16) = make_uint4(packhi(f00, f01), packhi(f10, f11),
                                                        packlo(f00, f01), packlo(f10, f11));
    }
    if ((le & 7) == 0) {
        int l = le >> 3;
        const float* b3p = b3 + (size_t)l * 2048;  // [8][256]
        unsigned char* bb = g_w + B3OFF + (size_t)l * 8192;
        for (int idx = t; idx < 1024; idx += 256) {
            int nt = idx >> 5, ln = idx & 31;
            int n = nt * 8 + ln / 4, e0 = (ln % 4) * 2;
            float v0 = b3p[e0 * 256 + n], v1 = b3p[(e0 + 1) * 256 + n];
            *(uint32_t*)(bb + idx * 4) = packhi(v0, v1);
            *(uint32_t*)(bb + 4096 + idx * 4) = packlo(v0, v1);
        }
    }
}

// ---------------- smem layout (bytes) ----------------
#define XFRAG 0          // 131072 (hi kt0-15, lo kt16-31)
#define BUFP  131072     // 32768 : W1hi -> h1 frags -> next W1hi
#define BUFQ  163840     // 32768 : W1lo -> W3i -> next W1lo
#define W2F   196608     // 8192 interleaved
#define H2F   204800     // 16384
#define WFA   221184     // 4096
#define WSOFT 225280     // 4096
#define B1S   229376     // 256
#define B2S   229632     // 128
#define SMEM_BYTES 229760
#define XLO 65536

__global__ void __launch_bounds__(NTH, 1)
moe_mma_kernel(const float* __restrict__ src,
               const float* __restrict__ b1, const float* __restrict__ b2,
               const float* __restrict__ masks, float* __restrict__ out)
{
    extern __shared__ char smem[];
    const uint32_t sbase = smem_to_u32(smem);
    const int tid = threadIdx.x;
    const int w = tid >> 5;
    const int ln = tid & 31;
    const int wm4 = w & 3;       // rowblock-pair (G1/G3)
    const int nq = w >> 2;       // n-quarter (G1/G3)
    const int rb = w >> 1;       // rowblock (G2)
    const int nhf = w & 1;       // n-half (G2)
    const int rowbase = blockIdx.x * TM;

    float* b1s = (float*)(smem + B1S);
    float* b2s = (float*)(smem + B2S);
    float* wsoft = (float*)(smem + WSOFT);
    uint32_t* xfrag = (uint32_t*)(smem + XFRAG);

    // prologue: preload W1hi_0 + W2i_0 as one group (role = "old C3")
    cpya(sbase + BUFP, g_w, 32768, tid);
    cpya(sbase + W2F, g_w + 65536, 8192, tid);
    CP_COMMIT;

    // initial X -> A-fragment image (4 threads per row)
    {
        const int r = tid >> 2;
        const int q4 = tid & 3;
        const float* sp = src + (size_t)(rowbase + r) * ND;
        const int rhalf = (r & 15) >> 3;
        #pragma unroll 4
        for (int p = 32 * q4; p < 32 * q4 + 32; p++) {
            float f0 = sp[2 * p], f1 = sp[2 * p + 1];
            int kt = p >> 3;
            int lane = 4 * (r & 7) + (p & 3);
            int khalf = (p & 7) >> 2;
            int reg = 2 * khalf + rhalf;
            int slot = ((kt * 8 + (r >> 4)) * 32 + lane) * 4 + reg;
            xfrag[slot] = packhi(f0, f1);
            xfrag[slot + (XLO >> 2)] = packlo(f0, f1);
        }
    }

    float xacc[2][8][4];

    for (int l = 0; l < NL; l++) {
        if (tid < TM) {
            const int r = tid;
            const float* mp = masks + ((size_t)l * NB + rowbase + r) * NE;
            float m[8], mx = -1e30f;
            #pragma unroll
            for (int e = 0; e < 8; e++) { m[e] = mp[e]; mx = fmaxf(mx, m[e]); }
            float s = 0.f;
            #pragma unroll
            for (int e = 0; e < 8; e++) { m[e] = expf(m[e] - mx); s += m[e]; }
            s = 1.f / s;
            #pragma unroll
            for (int e = 0; e < 8; e++) { m[e] *= s; wsoft[r * 8 + e] = m[e]; }
            uint32_t* wfa = (uint32_t*)(smem + WFA);
            const int rhalf = (r & 15) >> 3;
            #pragma unroll
            for (int q = 0; q < 4; q++) {
                int ub = (((r >> 4) * 32) + 4 * (r & 7) + q) * 4;
                wfa[ub + rhalf] = packhi(m[2 * q], m[2 * q + 1]);
                wfa[ub + 2 + rhalf] = packlo(m[2 * q], m[2 * q + 1]);
            }
        }
        #pragma unroll
        for (int i = 0; i < 2; i++)
            #pragma unroll
            for (int j = 0; j < 8; j++)
                #pragma unroll
                for (int q = 0; q < 4; q++) xacc[i][j][q] = 0.f;

        for (int e = 0; e < NE; e++) {
            const int idx = l * 8 + e;
            const unsigned char* wp = g_w + (size_t)idx * PER_LE;
            const unsigned char* wn = g_w + (size_t)(idx < 63 ? idx + 1 : 63) * PER_LE;

            // C1: W1lo -> Q (hides under G1 pass-hi)
            cpya(sbase + BUFQ, wp + 32768, 32768, tid);
            CP_COMMIT;
            CP_WAIT(1);                // old W1hi/W2 group done; W1lo still in flight
            __syncthreads();           // P=W1hi + W2F visible; Q writable was ensured last iter

            float bb1v = (tid < 64) ? b1[(size_t)idx * 64 + tid] : 0.f;
            float bb2v = (tid >= 64 && tid < 96) ? b2[(size_t)idx * 32 + tid - 64] : 0.f;

            // ---- G1 pass-hi: (Xhi+Xlo) * W1hi from P ----
            float c1[2][2][4];
            #pragma unroll
            for (int i = 0; i < 2; i++)
                #pragma unroll
                for (int j = 0; j < 2; j++)
                    #pragma unroll
                    for (int q = 0; q < 4; q++) c1[i][j][q] = 0.f;
            {
                const char* Pp = smem + BUFP;
                #pragma unroll 4
                for (int kt = 0; kt < 16; kt++) {
                    const char* xb = smem + XFRAG + ((kt * 8 + 2 * wm4) * 32 + ln) * 16;
                    uint4 a0h = *(const uint4*)xb;
                    uint4 a1h = *(const uint4*)(xb + 512);
                    uint4 a0l = *(const uint4*)(xb + XLO);
                    uint4 a1l = *(const uint4*)(xb + XLO + 512);
                    #pragma unroll
                    for (int nt = 0; nt < 2; nt++) {
                        uint2 bh = *(const uint2*)(Pp + ((kt * 8 + 2 * nq + nt) * 32 + ln) * 8);
                        MMA(c1[0][nt], a0h.x, a0h.y, a0h.z, a0h.w, bh.x, bh.y);
                        MMA(c1[1][nt], a1h.x, a1h.y, a1h.z, a1h.w, bh.x, bh.y);
                        MMA(c1[0][nt], a0l.x, a0l.y, a0l.z, a0l.w, bh.x, bh.y);
                        MMA(c1[1][nt], a1l.x, a1l.y, a1l.z, a1l.w, bh.x, bh.y);
                    }
                }
            }
            if (tid < 64) b1s[tid] = bb1v;
            else if (tid < 96) b2s[tid - 64] = bb2v;
            CP_WAIT(0);                // W1lo landed
            __syncthreads();

            // ---- G1 pass-lo: Xhi * W1lo from Q ----
            {
                const char* Qp = smem + BUFQ;
                #pragma unroll 4
                for (int kt = 0; kt < 16; kt++) {
                    const char* xb = smem + XFRAG + ((kt * 8 + 2 * wm4) * 32 + ln) * 16;
                    uint4 a0h = *(const uint4*)xb;
                    uint4 a1h = *(const uint4*)(xb + 512);
                    #pragma unroll
                    for (int nt = 0; nt < 2; nt++) {
                        uint2 bl = *(const uint2*)(Qp + ((kt * 8 + 2 * nq + nt) * 32 + ln) * 8);
                        MMA(c1[0][nt], a0h.x, a0h.y, a0h.z, a0h.w, bl.x, bl.y);
                        MMA(c1[1][nt], a1h.x, a1h.y, a1h.z, a1h.w, bl.x, bl.y);
                    }
                }
            }
            __syncthreads();           // P + Q readers done
            // C2: W3i -> Q (hides under D1-epi + G2)
            cpya(sbase + BUFQ, wp + 73728, 32768, tid);
            CP_COMMIT;

            // ---- D1 epilogue -> h1 frags into P ----
            {
                char* Pp = smem + BUFP;
                #pragma unroll
                for (int rt = 0; rt < 2; rt++) {
                    int rtg = 2 * wm4 + rt;
                    float v[2][4];
                    #pragma unroll
                    for (int nt = 0; nt < 2; nt++) {
                        int gc = 16 * nq + nt * 8 + (ln & 3) * 2;
                        float bb0 = b1s[gc], bb1 = b1s[gc + 1];
                        float* c = c1[rt][nt];
                        v[nt][0] = fmaxf(c[0] + bb0, 0.f);
                        v[nt][1] = fmaxf(c[1] + bb1, 0.f);
                        v[nt][2] = fmaxf(c[2] + bb0, 0.f);
                        v[nt][3] = fmaxf(c[3] + bb1, 0.f);
                    }
                    uint4 hi = make_uint4(packhi(v[0][0], v[0][1]), packhi(v[0][2], v[0][3]),
                                          packhi(v[1][0], v[1][1]), packhi(v[1][2], v[1][3]));
                    uint4 lo = make_uint4(packlo(v[0][0], v[0][1]), packlo(v[0][2], v[0][3]),
                                          packlo(v[1][0], v[1][1]), packlo(v[1][2], v[1][3]));
                    *(uint4*)(Pp + ((nq * 8 + rtg) * 32 + ln) * 16) = hi;
                    *(uint4*)(Pp + (((nq + 4) * 8 + rtg) * 32 + ln) * 16) = lo;
                }
            }
            __syncthreads();           // h1 visible

            // ---- G2: h1 (P) x W2 (interleaved) ----
            float c2[2][4];
            #pragma unroll
            for (int j = 0; j < 2; j++)
                #pragma unroll
                for (int q = 0; q < 4; q++) c2[j][q] = 0.f;
            {
                const char* Pp = smem + BUFP;
                #pragma unroll
                for (int kt = 0; kt < 4; kt++) {
                    uint4 ah = *(const uint4*)(Pp + ((kt * 8 + rb) * 32 + ln) * 16);
                    uint4 al = *(const uint4*)(Pp + (((kt + 4) * 8 + rb) * 32 + ln) * 16);
                    #pragma unroll
                    for (int nt = 0; nt < 2; nt++) {
                        int ntg = 2 * nhf + nt;
                        uint4 b = *(const uint4*)(smem + W2F + ((kt * 4 + ntg) * 32 + ln) * 16);
                        MMA(c2[nt], ah.x, ah.y, ah.z, ah.w, b.x, b.y);
                        MMA(c2[nt], al.x, al.y, al.z, al.w, b.x, b.y);
                        MMA(c2[nt], ah.x, ah.y, ah.z, ah.w, b.z, b.w);
                    }
                }
            }
            // ---- D2 epilogue -> h2 frags into H2F ----
            {
                float wg0 = wsoft[(16 * rb + ln / 4) * 8 + e];
                float wg1 = wsoft[(16 * rb + 8 + ln / 4) * 8 + e];
                float v[2][4];
                #pragma unroll
                for (int nt = 0; nt < 2; nt++) {
                    int gc = 16 * nhf + nt * 8 + (ln & 3) * 2;
                    float bb0 = b2s[gc], bb1 = b2s[gc + 1];
                    float* c = c2[nt];
                    v[nt][0] = fmaxf(c[0] + bb0, 0.f) * wg0;
                    v[nt][1] = fmaxf(c[1] + bb1, 0.f) * wg0;
                    v[nt][2] = fmaxf(c[2] + bb0, 0.f) * wg1;
                    v[nt][3] = fmaxf(c[3] + bb1, 0.f) * wg1;
                }
                uint4 hi = make_uint4(packhi(v[0][0], v[0][1]), packhi(v[0][2], v[0][3]),
                                      packhi(v[1][0], v[1][1]), packhi(v[1][2], v[1][3]));
                uint4 lo = make_uint4(packlo(v[0][0], v[0][1]), packlo(v[0][2], v[0][3]),
                                      packlo(v[1][0], v[1][1]), packlo(v[1][2], v[1][3]));
                *(uint4*)(smem + H2F + ((nhf * 8 + rb) * 32 + ln) * 16) = hi;
                *(uint4*)(smem + H2F + (((nhf + 2) * 8 + rb) * 32 + ln) * 16) = lo;
            }
            CP_WAIT(0);                // W3 (Q) landed
            __syncthreads();           // h2 + Q visible; P(h1), W2F dead
            // C3: next W1hi -> P, next W2i -> W2F (hides under G3)
            cpya(sbase + BUFP, wn, 32768, tid);
            cpya(sbase + W2F, wn + 65536, 8192, tid);
            CP_COMMIT;

            // ---- G3: h2 x W3 (B loaded once; A in regs) ----
            {
                const char* Qp = smem + BUFQ;
                const unsigned char* gb3 = g_w + B3OFF + (size_t)l * 8192;
                uint4 A[2][4];
                #pragma unroll
                for (int rt = 0; rt < 2; rt++) {
                    int rtg = 2 * wm4 + rt;
                    A[rt][0] = *(const uint4*)(smem + H2F + ((0 * 8 + rtg) * 32 + ln) * 16);
                    A[rt][1] = *(const uint4*)(smem + H2F + ((1 * 8 + rtg) * 32 + ln) * 16);
                    A[rt][2] = *(const uint4*)(smem + H2F + ((2 * 8 + rtg) * 32 + ln) * 16);
                    A[rt][3] = *(const uint4*)(smem + H2F + ((3 * 8 + rtg) * 32 + ln) * 16);
                }
                uint4 wf0 = *(const uint4*)(smem + WFA + ((2 * wm4) * 32 + ln) * 16);
                uint4 wf1 = *(const uint4*)(smem + WFA + ((2 * wm4 + 1) * 32 + ln) * 16);
                #pragma unroll
                for (int nt = 0; nt < 8; nt++) {
                    int gnt = 8 * nq + nt;
                    uint4 b0 = *(const uint4*)(Qp + ((0 * 32 + gnt) * 32 + ln) * 16);
                    uint4 b1v = *(const uint4*)(Qp + ((32 + gnt) * 32 + ln) * 16);
                    #pragma unroll
                    for (int rt = 0; rt < 2; rt++) {
                        float* cc = xacc[rt][nt];
                        MMA(cc, A[rt][0].x, A[rt][0].y, A[rt][0].z, A[rt][0].w, b0.x, b0.y);
                        MMA(cc, A[rt][1].x, A[rt][1].y, A[rt][1].z, A[rt][1].w, b1v.x, b1v.y);
                        MMA(cc, A[rt][2].x, A[rt][2].y, A[rt][2].z, A[rt][2].w, b0.x, b0.y);
                        MMA(cc, A[rt][3].x, A[rt][3].y, A[rt][3].z, A[rt][3].w, b1v.x, b1v.y);
                        MMA(cc, A[rt][0].x, A[rt][0].y, A[rt][0].z, A[rt][0].w, b0.z, b0.w);
                        MMA(cc, A[rt][1].x, A[rt][1].y, A[rt][1].z, A[rt][1].w, b1v.z, b1v.w);
                    }
                    if (e == 0) {
                        uint32_t p3h = *(const uint32_t*)(gb3 + (gnt * 32 + ln) * 4);
                        uint32_t p3l = *(const uint32_t*)(gb3 + 4096 + (gnt * 32 + ln) * 4);
                        MMA(xacc[0][nt], wf0.x, wf0.y, wf0.z, wf0.w, p3h, p3h);
                        MMA(xacc[0][nt], wf0.x, wf0.y, 0u, 0u, p3l, 0u);
                        MMA(xacc[1][nt], wf1.x, wf1.y, wf1.z, wf1.w, p3h, p3h);
                        MMA(xacc[1][nt], wf1.x, wf1.y, 0u, 0u, p3l, 0u);
                    }
                }
            }
            __syncthreads();           // Q/H2F readers done (next W1lo may target Q)
        } // experts

        // ---- layer end: xacc -> xfrag or out ----
        if (l == NL - 1) {
            #pragma unroll
            for (int rt = 0; rt < 2; rt++) {
                int r0 = 32 * wm4 + rt * 16 + ln / 4;
                #pragma unroll
                for (int nt = 0; nt < 8; nt++) {
                    int col = 64 * nq + nt * 8 + (ln & 3) * 2;
                    float* cc = xacc[rt][nt];
                    *(float2*)(out + (size_t)(rowbase + r0) * ND + col) = make_float2(cc[0], cc[1]);
                    *(float2*)(out + (size_t)(rowbase + r0 + 8) * ND + col) = make_float2(cc[2], cc[3]);
                }
            }
        } else {
            #pragma unroll
            for (int rt = 0; rt < 2; rt++) {
                int rtg = 2 * wm4 + rt;
                #pragma unroll
                for (int nt = 0; nt < 8; nt++) {
                    int kt = 4 * nq + (nt >> 1);
                    float* cc = xacc[rt][nt];
                    int sb = ((kt * 8 + rtg) * 32 + ln) * 4 + 2 * (nt & 1);
                    xfrag[sb] = packhi(cc[0], cc[1]);
                    xfrag[sb + 1] = packhi(cc[2], cc[3]);
                    xfrag[sb + (XLO >> 2)] = packlo(cc[0], cc[1]);
                    xfrag[sb + (XLO >> 2) + 1] = packlo(cc[2], cc[3]);
                }
            }
        }
    } // layers
    CP_WAIT(0);
}

extern "C" void kernel_launch(void* const* d_in, const int* in_sizes, int n_in,
                              void* d_out, int out_size)
{
    const float* src   = (const float*)d_in[0];
    const float* W1    = (const float*)d_in[1];
    const float* b1    = (const float*)d_in[2];
    const float* W2    = (const float*)d_in[3];
    const float* b2    = (const float*)d_in[4];
    const float* W3    = (const float*)d_in[5];
    const float* b3    = (const float*)d_in[6];
    const float* masks = (const float*)d_in[7];
    float* out = (float*)d_out;
    (void)in_sizes; (void)n_in; (void)out_size;

    prep_kernel<<<64, 256>>>(W1, W2, W3, b3);
    cudaFuncSetAttribute(moe_mma_kernel,
                         cudaFuncAttributeMaxDynamicSharedMemorySize, SMEM_BYTES);
    moe_mma_kernel<<<NB / TM, NTH, SMEM_BYTES>>>(src, b1, b2, masks, out);
}

// round 8
// speedup vs baseline: 1.8050x; 1.3452x over previous
#include <cuda_runtime.h>
#include <cuda_bf16.h>
#include <cstdint>
#include <math.h>

#define NL 8
#define NE 8
#define ND 256
#define NB 16384
#define TM 128
#define NTH 512

// ---------------- helpers ----------------
__device__ __forceinline__ uint32_t smem_to_u32(const void* p) {
    uint32_t a;
    asm("{ .reg .u64 t; cvta.to.shared.u64 t, %1; cvt.u32.u64 %0, t; }" : "=r"(a) : "l"(p));
    return a;
}
__host__ __device__ __forceinline__ uint32_t tf32c(float f) {
#ifdef __CUDA_ARCH__
    uint32_t u;
    asm("cvt.rna.tf32.f32 %0, %1;" : "=r"(u) : "f"(f));
    return u;
#else
    return 0;
#endif
}

#define MMAT(c, a0, a1, a2, a3, b0, b1) \
    asm volatile("mma.sync.aligned.m16n8k8.row.col.f32.tf32.tf32.f32 " \
        "{%0,%1,%2,%3},{%4,%5,%6,%7},{%8,%9},{%0,%1,%2,%3};" \
        : "+f"((c)[0]), "+f"((c)[1]), "+f"((c)[2]), "+f"((c)[3]) \
        : "r"(a0), "r"(a1), "r"(a2), "r"(a3), "r"(b0), "r"(b1))

#define CP_COMMIT asm volatile("cp.async.commit_group;" ::: "memory")
#define CP_WAIT(n) asm volatile("cp.async.wait_group %0;" :: "n"(n) : "memory")

__device__ __forceinline__ void cpya(uint32_t dst, const unsigned char* src, int bytes, int tid) {
    for (int i = tid * 16; i < bytes; i += NTH * 16)
        asm volatile("cp.async.cg.shared.global [%0], [%1], 16;" :: "r"(dst + i), "l"(src + i));
}

// ---------------- global weight images (tf32 fragments) ----------------
// per (l,e): W1a(kt0-15) 32768 | W1b(kt16-31) 32768 | W2 8192 | W3 32768
#define PER_LE 106496
#define B3OFF (64 * PER_LE)
__device__ __align__(16) unsigned char g_w[B3OFF + 8 * 8192];

__global__ void prep_kernel(const float* __restrict__ W1, const float* __restrict__ W2,
                            const float* __restrict__ W3, const float* __restrict__ b3) {
    const int le = blockIdx.x;
    const int t = threadIdx.x;
    unsigned char* base = g_w + (size_t)le * PER_LE;

    const float* W1p = W1 + (size_t)le * 16384;   // [64][256]
    for (int idx = t; idx < 8192; idx += 256) {   // (ktG 0..31, nt 0..7, ln)
        int ktG = idx >> 8, nt = (idx >> 5) & 7, ln = idx & 31;
        int g = ln >> 2, tig = ln & 3;
        int n = nt * 8 + g;
        uint32_t b0 = tf32c(W1p[n * 256 + ktG * 8 + tig]);
        uint32_t b1 = tf32c(W1p[n * 256 + ktG * 8 + tig + 4]);
        int off = (ktG < 16) ? (((ktG * 8 + nt) * 32 + ln) * 8)
                             : (32768 + (((ktG - 16) * 8 + nt) * 32 + ln) * 8);
        *(uint2*)(base + off) = make_uint2(b0, b1);
    }
    const float* W2p = W2 + (size_t)le * 2048;    // [32][64]
    for (int idx = t; idx < 1024; idx += 256) {   // (kt 0..7, nt 0..3, ln)
        int kt = idx >> 7, nt = (idx >> 5) & 3, ln = idx & 31;
        int g = ln >> 2, tig = ln & 3;
        int n = nt * 8 + g;
        *(uint2*)(base + 65536 + idx * 8) =
            make_uint2(tf32c(W2p[n * 64 + kt * 8 + tig]),
                       tf32c(W2p[n * 64 + kt * 8 + tig + 4]));
    }
    const float* W3p = W3 + (size_t)le * 8192;    // [256][32]
    for (int idx = t; idx < 4096; idx += 256) {   // (kt 0..3, nt 0..31, ln)
        int kt = idx >> 10, nt = (idx >> 5) & 31, ln = idx & 31;
        int g = ln >> 2, tig = ln & 3;
        int n = nt * 8 + g;
        *(uint2*)(base + 73728 + idx * 8) =
            make_uint2(tf32c(W3p[n * 32 + kt * 8 + tig]),
                       tf32c(W3p[n * 32 + kt * 8 + tig + 4]));
    }
    if ((le & 7) == 0) {
        int l = le >> 3;
        const float* b3p = b3 + (size_t)l * 2048;  // [8][256]
        unsigned char* bb = g_w + B3OFF + (size_t)l * 8192;
        for (int idx = t; idx < 1024; idx += 256) {  // (nt 0..31, ln)
            int nt = idx >> 5, ln = idx & 31;
            int g = ln >> 2, tig = ln & 3;
            int n = nt * 8 + g;
            *(uint2*)(bb + idx * 8) =
                make_uint2(tf32c(b3p[tig * 256 + n]), tf32c(b3p[(tig + 4) * 256 + n]));
        }
    }
}

// ---------------- smem layout (bytes) ----------------
#define XFRAG 0          // 131072: X A-frags uint4 [(kt*8+rt)*32+ln]
#define BUFP  131072     // 32768 : W1a -> h1 planes (4 x 8192) -> next W1a
#define BUFQ  163840     // 32768 : W1b -> W3 -> next W1b
#define W2F   196608     // 8192
#define H2F   204800     // 16384: h2 planes (4 x 4096)
#define WFA   221184     // 4096 : softmax A-frags uint4 [rt*32+ln]
#define WSOFT 225280     // 4096
#define B1S   229376     // 256
#define B2S   229632     // 128
#define SMEM_BYTES 229760

__global__ void __launch_bounds__(NTH, 1)
moe_mma_kernel(const float* __restrict__ src,
               const float* __restrict__ b1, const float* __restrict__ b2,
               const float* __restrict__ masks, float* __restrict__ out)
{
    extern __shared__ char smem[];
    const uint32_t sbase = smem_to_u32(smem);
    const int tid = threadIdx.x;
    const int w = tid >> 5;
    const int ln = tid & 31;
    const int g = ln >> 2;
    const int tig = ln & 3;
    const int wm4 = w & 3;       // rowblock-pair (G1/G3)
    const int nq = w >> 2;       // n-quarter (G1/G3)
    const int rb = w >> 1;       // rowblock (G2)
    const int nhf = w & 1;       // n-half (G2)
    const int rowbase = blockIdx.x * TM;

    float* b1s = (float*)(smem + B1S);
    float* b2s = (float*)(smem + B2S);
    float* wsoft = (float*)(smem + WSOFT);
    uint32_t* xfrag = (uint32_t*)(smem + XFRAG);

    // prologue: preload W1a_0 + W2_0 as one group (role = "old C3")
    cpya(sbase + BUFP, g_w, 32768, tid);
    cpya(sbase + W2F, g_w + 65536, 8192, tid);
    CP_COMMIT;

    // initial X -> tf32 A-fragment image (4 threads per row)
    {
        const int r = tid >> 2;
        const int q4 = tid & 3;
        const float* sp = src + (size_t)(rowbase + r) * ND;
        const int rt = r >> 4;
        const int rh = ((r & 15) >= 8) ? 1 : 0;
        #pragma unroll 4
        for (int c = 64 * q4; c < 64 * q4 + 64; c++) {
            int kt = c >> 3;
            int lane = 4 * (r & 7) + (c & 3);
            int reg = rh + 2 * (((c & 7) >= 4) ? 1 : 0);
            xfrag[((kt * 8 + rt) * 32 + lane) * 4 + reg] = tf32c(sp[c]);
        }
    }

    float xacc[2][8][4];

    for (int l = 0; l < NL; l++) {
        if (tid < TM) {
            const int r = tid;
            const float* mp = masks + ((size_t)l * NB + rowbase + r) * NE;
            float m[8], mx = -1e30f;
            #pragma unroll
            for (int e = 0; e < 8; e++) { m[e] = mp[e]; mx = fmaxf(mx, m[e]); }
            float s = 0.f;
            #pragma unroll
            for (int e = 0; e < 8; e++) { m[e] = expf(m[e] - mx); s += m[e]; }
            s = 1.f / s;
            #pragma unroll
            for (int e = 0; e < 8; e++) { m[e] *= s; wsoft[r * 8 + e] = m[e]; }
            // softmax A-frags (K=8 experts) for the b3 MMA
            uint32_t* wfa = (uint32_t*)(smem + WFA);
            const int rt = r >> 4;
            const int rh = ((r & 15) >= 8) ? 1 : 0;
            #pragma unroll
            for (int e = 0; e < 8; e++) {
                int lane = 4 * (r & 7) + (e & 3);
                int reg = rh + 2 * (e >= 4 ? 1 : 0);
                wfa[(rt * 32 + lane) * 4 + reg] = tf32c(m[e]);
            }
        }
        #pragma unroll
        for (int i = 0; i < 2; i++)
            #pragma unroll
            for (int j = 0; j < 8; j++)
                #pragma unroll
                for (int q = 0; q < 4; q++) xacc[i][j][q] = 0.f;

        for (int e = 0; e < NE; e++) {
            const int idx = l * 8 + e;
            const unsigned char* wp = g_w + (size_t)idx * PER_LE;
            const unsigned char* wn = g_w + (size_t)(idx < 63 ? idx + 1 : 63) * PER_LE;

            // C1: W1b -> Q (hides under G1a)
            cpya(sbase + BUFQ, wp + 32768, 32768, tid);
            CP_COMMIT;
            CP_WAIT(1);                // old C3 (W1a->P, W2) done
            __syncthreads();

            float bb1v = (tid < 64) ? b1[(size_t)idx * 64 + tid] : 0.f;
            float bb2v = (tid >= 64 && tid < 96) ? b2[(size_t)idx * 32 + tid - 64] : 0.f;

            // ---- G1a: kt 0..15 from P ----
            float c1[2][2][4];
            #pragma unroll
            for (int i = 0; i < 2; i++)
                #pragma unroll
                for (int j = 0; j < 2; j++)
                    #pragma unroll
                    for (int q = 0; q < 4; q++) c1[i][j][q] = 0.f;
            {
                const char* Pp = smem + BUFP;
                #pragma unroll 4
                for (int kt = 0; kt < 16; kt++) {
                    const char* xb = smem + XFRAG + ((kt * 8 + 2 * wm4) * 32 + ln) * 16;
                    uint4 a0 = *(const uint4*)xb;
                    uint4 a1 = *(const uint4*)(xb + 512);
                    #pragma unroll
                    for (int nt = 0; nt < 2; nt++) {
                        uint2 b = *(const uint2*)(Pp + ((kt * 8 + 2 * nq + nt) * 32 + ln) * 8);
                        MMAT(c1[0][nt], a0.x, a0.y, a0.z, a0.w, b.x, b.y);
                        MMAT(c1[1][nt], a1.x, a1.y, a1.z, a1.w, b.x, b.y);
                    }
                }
            }
            if (tid < 64) b1s[tid] = bb1v;
            else if (tid < 96) b2s[tid - 64] = bb2v;
            CP_WAIT(0);                // W1b landed
            __syncthreads();

            // ---- G1b: kt 16..31 from Q ----
            {
                const char* Qp = smem + BUFQ;
                #pragma unroll 4
                for (int kt = 16; kt < 32; kt++) {
                    const char* xb = smem + XFRAG + ((kt * 8 + 2 * wm4) * 32 + ln) * 16;
                    uint4 a0 = *(const uint4*)xb;
                    uint4 a1 = *(const uint4*)(xb + 512);
                    #pragma unroll
                    for (int nt = 0; nt < 2; nt++) {
                        uint2 b = *(const uint2*)(Qp + (((kt - 16) * 8 + 2 * nq + nt) * 32 + ln) * 8);
                        MMAT(c1[0][nt], a0.x, a0.y, a0.z, a0.w, b.x, b.y);
                        MMAT(c1[1][nt], a1.x, a1.y, a1.z, a1.w, b.x, b.y);
                    }
                }
            }
            __syncthreads();           // P + Q readers done
            // C2: W3 -> Q (hides under D1epi + G2)
            cpya(sbase + BUFQ, wp + 73728, 32768, tid);
            CP_COMMIT;

            // ---- D1 epilogue: bias+relu, cvt tf32 -> h1 planes in P ----
            {
                char* Pp = smem + BUFP;
                #pragma unroll
                for (int rt = 0; rt < 2; rt++) {
                    #pragma unroll
                    for (int nt = 0; nt < 2; nt++) {
                        int tile = (2 * nq + nt) * 8 + (2 * wm4 + rt);
                        float* c = c1[rt][nt];
                        #pragma unroll
                        for (int ci = 0; ci < 4; ci++) {
                            int bb = ci & 1, rh = ci >> 1;
                            int h = 16 * nq + 8 * nt + 2 * tig + bb;
                            float v = fmaxf(c[ci] + b1s[h], 0.f);
                            int plane = rh + 2 * (tig >> 1);
                            int lanep = 4 * g + ((2 * tig + bb) & 3);
                            *(uint32_t*)(Pp + plane * 8192 + (tile * 32 + lanep) * 4) = tf32c(v);
                        }
                    }
                }
            }
            __syncthreads();           // h1 visible

            // ---- G2: h1 (P planes) x W2 ----
            float c2[2][4];
            #pragma unroll
            for (int j = 0; j < 2; j++)
                #pragma unroll
                for (int q = 0; q < 4; q++) c2[j][q] = 0.f;
            {
                const char* Pp = smem + BUFP;
                #pragma unroll
                for (int kt = 0; kt < 8; kt++) {
                    int off = ((kt * 8 + rb) * 32 + ln) * 4;
                    uint32_t a0 = *(const uint32_t*)(Pp + off);
                    uint32_t a1 = *(const uint32_t*)(Pp + 8192 + off);
                    uint32_t a2 = *(const uint32_t*)(Pp + 16384 + off);
                    uint32_t a3 = *(const uint32_t*)(Pp + 24576 + off);
                    #pragma unroll
                    for (int nt = 0; nt < 2; nt++) {
                        int ntg = 2 * nhf + nt;
                        uint2 b = *(const uint2*)(smem + W2F + ((kt * 4 + ntg) * 32 + ln) * 8);
                        MMAT(c2[nt], a0, a1, a2, a3, b.x, b.y);
                    }
                }
            }
            // ---- D2 epilogue: bias+relu, *softmax, cvt -> h2 planes ----
            {
                float wg0 = wsoft[(16 * rb + g) * 8 + e];
                float wg1 = wsoft[(16 * rb + 8 + g) * 8 + e];
                #pragma unroll
                for (int nt = 0; nt < 2; nt++) {
                    int tile = (2 * nhf + nt) * 8 + rb;
                    float* c = c2[nt];
                    #pragma unroll
                    for (int ci = 0; ci < 4; ci++) {
                        int bb = ci & 1, rh = ci >> 1;
                        int h = 16 * nhf + 8 * nt + 2 * tig + bb;
                        float v = fmaxf(c[ci] + b2s[h], 0.f) * (rh ? wg1 : wg0);
                        int plane = rh + 2 * (tig >> 1);
                        int lanep = 4 * g + ((2 * tig + bb) & 3);
                        *(uint32_t*)(smem + H2F + plane * 4096 + (tile * 32 + lanep) * 4) = tf32c(v);
                    }
                }
            }
            CP_WAIT(0);                // W3 (Q) landed
            __syncthreads();           // h2 + Q visible; P(h1), W2F dead
            // C3: next W1a -> P, next W2 -> W2F (hides under G3)
            cpya(sbase + BUFP, wn, 32768, tid);
            cpya(sbase + W2F, wn + 65536, 8192, tid);
            CP_COMMIT;

            // ---- G3: h2 (planes) x W3 (Q) -> xacc ----
            {
                const char* Qp = smem + BUFQ;
                #pragma unroll
                for (int kt = 0; kt < 4; kt++) {
                    int off = ((kt * 8 + 2 * wm4) * 32 + ln) * 4;
                    uint32_t A0[4], A1[4];
                    #pragma unroll
                    for (int p = 0; p < 4; p++) {
                        A0[p] = *(const uint32_t*)(smem + H2F + p * 4096 + off);
                        A1[p] = *(const uint32_t*)(smem + H2F + p * 4096 + off + 128);
                    }
                    #pragma unroll
                    for (int nt = 0; nt < 8; nt++) {
                        int gnt = 8 * nq + nt;
                        uint2 b = *(const uint2*)(Qp + ((kt * 32 + gnt) * 32 + ln) * 8);
                        MMAT(xacc[0][nt], A0[0], A0[1], A0[2], A0[3], b.x, b.y);
                        MMAT(xacc[1][nt], A1[0], A1[1], A1[2], A1[3], b.x, b.y);
                    }
                }
                if (e == 0) {   // weighted-b3 term via single K=8 MMA per tile
                    const unsigned char* gb3 = g_w + B3OFF + (size_t)l * 8192;
                    uint4 wf0 = *(const uint4*)(smem + WFA + ((2 * wm4) * 32 + ln) * 16);
                    uint4 wf1 = *(const uint4*)(smem + WFA + ((2 * wm4 + 1) * 32 + ln) * 16);
                    #pragma unroll
                    for (int nt = 0; nt < 8; nt++) {
                        int gnt = 8 * nq + nt;
                        uint2 pb = *(const uint2*)(gb3 + (gnt * 32 + ln) * 8);
                        MMAT(xacc[0][nt], wf0.x, wf0.y, wf0.z, wf0.w, pb.x, pb.y);
                        MMAT(xacc[1][nt], wf1.x, wf1.y, wf1.z, wf1.w, pb.x, pb.y);
                    }
                }
            }
            __syncthreads();           // Q/H2F readers done
        } // experts

        // ---- layer end: xacc -> xfrag or out ----
        if (l == NL - 1) {
            #pragma unroll
            for (int rt = 0; rt < 2; rt++) {
                int r0 = 32 * wm4 + rt * 16 + g;
                #pragma unroll
                for (int nt = 0; nt < 8; nt++) {
                    int col = 64 * nq + nt * 8 + tig * 2;
                    float* cc = xacc[rt][nt];
                    *(float2*)(out + (size_t)(rowbase + r0) * ND + col) = make_float2(cc[0], cc[1]);
                    *(float2*)(out + (size_t)(rowbase + r0 + 8) * ND + col) = make_float2(cc[2], cc[3]);
                }
            }
        } else {
            #pragma unroll
            for (int rt = 0; rt < 2; rt++) {
                int rtile = 2 * wm4 + rt;
                #pragma unroll
                for (int nt = 0; nt < 8; nt++) {
                    int kt = 8 * nq + nt;
                    float* cc = xacc[rt][nt];
                    #pragma unroll
                    for (int ci = 0; ci < 4; ci++) {
                        int bb = ci & 1, rh = ci >> 1;
                        int lanep = 4 * g + ((2 * tig + bb) & 3);
                        int reg = rh + 2 * (tig >> 1);
                        xfrag[((kt * 8 + rtile) * 32 + lanep) * 4 + reg] = tf32c(cc[ci]);
                    }
                }
            }
        }
    } // layers
    CP_WAIT(0);
}

extern "C" void kernel_launch(void* const* d_in, const int* in_sizes, int n_in,
                              void* d_out, int out_size)
{
    const float* src   = (const float*)d_in[0];
    const float* W1    = (const float*)d_in[1];
    const float* b1    = (const float*)d_in[2];
    const float* W2    = (const float*)d_in[3];
    const float* b2    = (const float*)d_in[4];
    const float* W3    = (const float*)d_in[5];
    const float* b3    = (const float*)d_in[6];
    const float* masks = (const float*)d_in[7];
    float* out = (float*)d_out;
    (void)in_sizes; (void)n_in; (void)out_size;

    prep_kernel<<<64, 256>>>(W1, W2, W3, b3);
    cudaFuncSetAttribute(moe_mma_kernel,
                         cudaFuncAttributeMaxDynamicSharedMemorySize, SMEM_BYTES);
    moe_mma_kernel<<<NB / TM, NTH, SMEM_BYTES>>>(src, b1, b2, masks, out);
}

// round 10
// speedup vs baseline: 2.2081x; 1.2233x over previous
#include <cuda_runtime.h>
#include <cuda_fp16.h>
#include <cstdint>
#include <math.h>

#define NL 8
#define NE 8
#define ND 256
#define NB 16384
#define TM 128
#define NTH 512

// ---------------- helpers ----------------
__device__ __forceinline__ uint32_t smem_to_u32(const void* p) {
    uint32_t a;
    asm("{ .reg .u64 t; cvta.to.shared.u64 t, %1; cvt.u32.u64 %0, t; }" : "=r"(a) : "l"(p));
    return a;
}
__device__ __forceinline__ uint32_t h2pk(float a, float b) {
    __half2 h = __floats2half2_rn(a, b);
    return *(uint32_t*)&h;
}
// exact split: a = hi + lo (both fp16), packed pairwise
__device__ __forceinline__ void split2(float a, float b, uint32_t& hi, uint32_t& lo) {
    __half ha = __float2half_rn(a), hb = __float2half_rn(b);
    __half2 hh = __halves2half2(ha, hb);
    hi = *(uint32_t*)&hh;
    lo = h2pk(a - __half2float(ha), b - __half2float(hb));
}

#define MMA16(c, A, b0, b1) \
    asm volatile("mma.sync.aligned.m16n8k16.row.col.f32.f16.f16.f32 " \
        "{%0,%1,%2,%3},{%4,%5,%6,%7},{%8,%9},{%0,%1,%2,%3};" \
        : "+f"((c)[0]), "+f"((c)[1]), "+f"((c)[2]), "+f"((c)[3]) \
        : "r"((A).x), "r"((A).y), "r"((A).z), "r"((A).w), "r"(b0), "r"(b1))

#define MMA8(c, a0, a1, b0) \
    asm volatile("mma.sync.aligned.m16n8k8.row.col.f32.f16.f16.f32 " \
        "{%0,%1,%2,%3},{%4,%5},{%6},{%0,%1,%2,%3};" \
        : "+f"((c)[0]), "+f"((c)[1]), "+f"((c)[2]), "+f"((c)[3]) \
        : "r"(a0), "r"(a1), "r"(b0))

#define CP_COMMIT asm volatile("cp.async.commit_group;" ::: "memory")
#define CP_WAIT(n) asm volatile("cp.async.wait_group %0;" :: "n"(n) : "memory")

__device__ __forceinline__ void cpya(uint32_t dst, const unsigned char* src, int bytes, int tid) {
    for (int i = tid * 16; i < bytes; i += NTH * 16)
        asm volatile("cp.async.cg.shared.global [%0], [%1], 16;" :: "r"(dst + i), "l"(src + i));
}

// ---------------- global weight images (fp16 B-fragments) ----------------
// per (l,e): W1 32768 (kb-major, halves = 16KB each) | W2 4096 | W3 16384
#define PER_LE 53248
#define B3OFF (64 * PER_LE)
__device__ __align__(16) unsigned char g_w[B3OFF + 8 * 4096];

__global__ void prep_kernel(const float* __restrict__ W1, const float* __restrict__ W2,
                            const float* __restrict__ W3, const float* __restrict__ b3) {
    const int le = blockIdx.x;
    const int t = threadIdx.x;
    unsigned char* base = g_w + (size_t)le * PER_LE;

    const float* W1p = W1 + (size_t)le * 16384;   // [64][256]
    for (int idx = t; idx < 4096; idx += 256) {   // (kb 0..15, nt 0..7, ln)
        int kb = idx >> 8, nt = (idx >> 5) & 7, ln = idx & 31;
        int g = ln >> 2, tig = ln & 3;
        int n = nt * 8 + g, k = kb * 16 + 2 * tig;
        *(uint2*)(base + idx * 8) = make_uint2(
            h2pk(W1p[n * 256 + k], W1p[n * 256 + k + 1]),
            h2pk(W1p[n * 256 + k + 8], W1p[n * 256 + k + 9]));
    }
    const float* W2p = W2 + (size_t)le * 2048;    // [32][64]
    for (int idx = t; idx < 512; idx += 256) {    // (kb 0..3, nt 0..3, ln)
        int kb = idx >> 7, nt = (idx >> 5) & 3, ln = idx & 31;
        int g = ln >> 2, tig = ln & 3;
        int n = nt * 8 + g, k = kb * 16 + 2 * tig;
        *(uint2*)(base + 32768 + idx * 8) = make_uint2(
            h2pk(W2p[n * 64 + k], W2p[n * 64 + k + 1]),
            h2pk(W2p[n * 64 + k + 8], W2p[n * 64 + k + 9]));
    }
    const float* W3p = W3 + (size_t)le * 8192;    // [256][32]
    for (int idx = t; idx < 2048; idx += 256) {   // (kb 0..1, nt 0..31, ln)
        int kb = idx >> 10, nt = (idx >> 5) & 31, ln = idx & 31;
        int g = ln >> 2, tig = ln & 3;
        int n = nt * 8 + g, k = kb * 16 + 2 * tig;
        *(uint2*)(base + 36864 + idx * 8) = make_uint2(
            h2pk(W3p[n * 32 + k], W3p[n * 32 + k + 1]),
            h2pk(W3p[n * 32 + k + 8], W3p[n * 32 + k + 9]));
    }
    if ((le & 7) == 0) {
        int l = le >> 3;
        const float* b3p = b3 + (size_t)l * 2048;  // [8][256]
        unsigned char* bb = g_w + B3OFF + (size_t)l * 4096;
        for (int idx = t; idx < 1024; idx += 256) {  // (nt 0..31, ln)
            int nt = idx >> 5, ln = idx & 31;
            int g = ln >> 2, tig = ln & 3;
            int n = nt * 8 + g;
            *(uint32_t*)(bb + idx * 4) = h2pk(b3p[2 * tig * 256 + n], b3p[(2 * tig + 1) * 256 + n]);
        }
    }
}

// ---------------- smem layout (bytes) ----------------
#define XFRAG 0          // 131072: X A-frags uint4 [((plane*16+kb)*8+rt)*32+ln]
#define BUF0  131072     // 16384
#define BUF1  147456     // 16384
#define H1F   163840     // 32768: [((plane*4+kb)*8+rt)*32+ln] uint4
#define H2F   196608     // 16384: [((plane*2+kb)*8+rt)*32+ln] uint4
#define W2F   212992     // 4096
#define WSOFT 217088     // 4096
#define B1S   221184     // 256
#define B2S   221440     // 128
#define SMEM_BYTES 221568

__global__ void __launch_bounds__(NTH, 1)
moe_mma_kernel(const float* __restrict__ src,
               const float* __restrict__ b1, const float* __restrict__ b2,
               const float* __restrict__ masks, float* __restrict__ out)
{
    extern __shared__ char smem[];
    const uint32_t sbase = smem_to_u32(smem);
    const int tid = threadIdx.x;
    const int w = tid >> 5;
    const int ln = tid & 31;
    const int g = ln >> 2;
    const int tig = ln & 3;
    const int wm4 = w & 3;       // rowblock-pair (G1/G3)
    const int nq = w >> 2;       // n-quarter (G1/G3)
    const int rb = w >> 1;       // rowblock (G2)
    const int nhf = w & 1;       // n-half (G2)
    const int rowbase = blockIdx.x * TM;

    float* b1s = (float*)(smem + B1S);
    float* b2s = (float*)(smem + B2S);
    float* wsoft = (float*)(smem + WSOFT);

    // prologue: stage W1a(0) + W2(0) as one group (plays role of "prev G3" group)
    cpya(sbase + BUF0, g_w, 16384, tid);
    cpya(sbase + W2F, g_w + 32768, 4096, tid);
    CP_COMMIT;

    // initial X -> fp16 hi/lo A-fragment image (4 threads per row)
    {
        const int r = tid >> 2;
        const int q4 = tid & 3;
        const float* sp = src + (size_t)(rowbase + r) * ND;
        const int rt = r >> 4;
        const int rsel = ((r & 15) >= 8) ? 1 : 0;
        #pragma unroll 4
        for (int c = 64 * q4; c < 64 * q4 + 64; c += 2) {
            int kb = c >> 4, kk = c & 15;
            int tigw = (kk & 7) >> 1;
            int reg = rsel + ((kk >= 8) ? 2 : 0);
            uint32_t hi, lo;
            split2(sp[c], sp[c + 1], hi, lo);
            uint32_t off = (uint32_t)((kb * 8 + rt) * 512 + (4 * (r & 7) + tigw) * 16 + reg * 4);
            *(uint32_t*)(smem + XFRAG + off) = hi;
            *(uint32_t*)(smem + XFRAG + 65536 + off) = lo;
        }
    }

    uint32_t Aoff = BUF0, Boff = BUF1;
    float xacc[2][8][4];

    for (int l = 0; l < NL; l++) {
        if (tid < TM) {
            const int r = tid;
            const float* mp = masks + ((size_t)l * NB + rowbase + r) * NE;
            float m[8], mx = -1e30f;
            #pragma unroll
            for (int e = 0; e < 8; e++) { m[e] = mp[e]; mx = fmaxf(mx, m[e]); }
            float s = 0.f;
            #pragma unroll
            for (int e = 0; e < 8; e++) { m[e] = expf(m[e] - mx); s += m[e]; }
            s = 1.f / s;
            #pragma unroll
            for (int e = 0; e < 8; e++) wsoft[r * 8 + e] = m[e] * s;
        }
        #pragma unroll
        for (int i = 0; i < 2; i++)
            #pragma unroll
            for (int j = 0; j < 8; j++)
                #pragma unroll
                for (int q = 0; q < 4; q++) xacc[i][j][q] = 0.f;

        for (int e = 0; e < NE; e++) {
            const int idx = l * 8 + e;
            const unsigned char* wp = g_w + (size_t)idx * PER_LE;
            const unsigned char* wn = g_w + (size_t)(idx < 63 ? idx + 1 : 63) * PER_LE;

            // C1: W1b -> B (hides under G1a)
            cpya(sbase + Boff, wp + 16384, 16384, tid);
            CP_COMMIT;
            CP_WAIT(1);                // prev-G3 group (W1a, W2) done
            __syncthreads();

            float bb1v = (tid < 64) ? b1[(size_t)idx * 64 + tid] : 0.f;
            float bb2v = (tid >= 64 && tid < 96) ? b2[(size_t)idx * 32 + tid - 64] : 0.f;

            // ---- G1a: kb 0..7 from A ----
            float c1[2][2][4];
            #pragma unroll
            for (int i = 0; i < 2; i++)
                #pragma unroll
                for (int j = 0; j < 2; j++)
                    #pragma unroll
                    for (int q = 0; q < 4; q++) c1[i][j][q] = 0.f;
            {
                const char* Ap = smem + Aoff;
                #pragma unroll
                for (int kb = 0; kb < 8; kb++) {
                    const char* xb = smem + XFRAG + (kb * 8 + 2 * wm4) * 512 + ln * 16;
                    uint4 Ah0 = *(const uint4*)xb;
                    uint4 Ah1 = *(const uint4*)(xb + 512);
                    uint4 Al0 = *(const uint4*)(xb + 65536);
                    uint4 Al1 = *(const uint4*)(xb + 65536 + 512);
                    #pragma unroll
                    for (int nt = 0; nt < 2; nt++) {
                        uint2 b = *(const uint2*)(Ap + ((kb * 8 + 2 * nq + nt) * 32 + ln) * 8);
                        MMA16(c1[0][nt], Ah0, b.x, b.y);
                        MMA16(c1[1][nt], Ah1, b.x, b.y);
                        MMA16(c1[0][nt], Al0, b.x, b.y);
                        MMA16(c1[1][nt], Al1, b.x, b.y);
                    }
                }
            }
            if (tid < 64) b1s[tid] = bb1v;
            else if (tid < 96) b2s[tid - 64] = bb2v;
            CP_WAIT(0);                // W1b landed
            __syncthreads();

            // ---- G1b: kb 8..15 from B ----
            {
                const char* Bp = smem + Boff;
                #pragma unroll
                for (int kb = 8; kb < 16; kb++) {
                    const char* xb = smem + XFRAG + (kb * 8 + 2 * wm4) * 512 + ln * 16;
                    uint4 Ah0 = *(const uint4*)xb;
                    uint4 Ah1 = *(const uint4*)(xb + 512);
                    uint4 Al0 = *(const uint4*)(xb + 65536);
                    uint4 Al1 = *(const uint4*)(xb + 65536 + 512);
                    #pragma unroll
                    for (int nt = 0; nt < 2; nt++) {
                        uint2 b = *(const uint2*)(Bp + (((kb - 8) * 8 + 2 * nq + nt) * 32 + ln) * 8);
                        MMA16(c1[0][nt], Ah0, b.x, b.y);
                        MMA16(c1[1][nt], Ah1, b.x, b.y);
                        MMA16(c1[0][nt], Al0, b.x, b.y);
                        MMA16(c1[1][nt], Al1, b.x, b.y);
                    }
                }
            }
            // C2: W3 -> A (A readers all done at prior barrier; hides under epi+G2)
            cpya(sbase + Aoff, wp + 36864, 16384, tid);
            CP_COMMIT;

            // ---- D1 epilogue: bias+relu, split, pack own regs -> H1F ----
            {
                #pragma unroll
                for (int rt = 0; rt < 2; rt++) {
                    float v[2][4];
                    #pragma unroll
                    for (int nt = 0; nt < 2; nt++)
                        #pragma unroll
                        for (int ci = 0; ci < 4; ci++) {
                            int h = 16 * nq + 8 * nt + 2 * tig + (ci & 1);
                            v[nt][ci] = fmaxf(c1[rt][nt][ci] + b1s[h], 0.f);
                        }
                    uint4 HI, LO;
                    split2(v[0][0], v[0][1], HI.x, LO.x);
                    split2(v[0][2], v[0][3], HI.y, LO.y);
                    split2(v[1][0], v[1][1], HI.z, LO.z);
                    split2(v[1][2], v[1][3], HI.w, LO.w);
                    uint32_t off = (uint32_t)((nq * 8 + 2 * wm4 + rt) * 512 + ln * 16);
                    *(uint4*)(smem + H1F + off) = HI;
                    *(uint4*)(smem + H1F + 16384 + off) = LO;
                }
            }
            __syncthreads();           // h1 visible

            // ---- G2: h1 (H1F) x W2 ----
            float c2[2][4];
            #pragma unroll
            for (int j = 0; j < 2; j++)
                #pragma unroll
                for (int q = 0; q < 4; q++) c2[j][q] = 0.f;
            {
                #pragma unroll
                for (int kb = 0; kb < 4; kb++) {
                    uint32_t off = (uint32_t)((kb * 8 + rb) * 512 + ln * 16);
                    uint4 Ah = *(const uint4*)(smem + H1F + off);
                    uint4 Al = *(const uint4*)(smem + H1F + 16384 + off);
                    #pragma unroll
                    for (int nt = 0; nt < 2; nt++) {
                        uint2 b = *(const uint2*)(smem + W2F + ((kb * 4 + 2 * nhf + nt) * 32 + ln) * 8);
                        MMA16(c2[nt], Ah, b.x, b.y);
                        MMA16(c2[nt], Al, b.x, b.y);
                    }
                }
            }
            // ---- D2 epilogue: bias+relu, *softmax, split -> H2F ----
            {
                float wg0 = wsoft[(16 * rb + g) * 8 + e];
                float wg1 = wsoft[(16 * rb + 8 + g) * 8 + e];
                float v[2][4];
                #pragma unroll
                for (int nt = 0; nt < 2; nt++)
                    #pragma unroll
                    for (int ci = 0; ci < 4; ci++) {
                        int h = 16 * nhf + 8 * nt + 2 * tig + (ci & 1);
                        v[nt][ci] = fmaxf(c2[nt][ci] + b2s[h], 0.f) * ((ci < 2) ? wg0 : wg1);
                    }
                uint4 HI, LO;
                split2(v[0][0], v[0][1], HI.x, LO.x);
                split2(v[0][2], v[0][3], HI.y, LO.y);
                split2(v[1][0], v[1][1], HI.z, LO.z);
                split2(v[1][2], v[1][3], HI.w, LO.w);
                uint32_t off = (uint32_t)((nhf * 8 + rb) * 512 + ln * 16);
                *(uint4*)(smem + H2F + off) = HI;
                *(uint4*)(smem + H2F + 8192 + off) = LO;
            }
            CP_WAIT(0);                // W3 (A) landed
            __syncthreads();           // h2 + W3 visible; H1F, W2F dead
            // C3: next W1a -> B, next W2 -> W2F (hides under G3; waited next expert)
            cpya(sbase + Boff, wn, 16384, tid);
            cpya(sbase + W2F, wn + 32768, 4096, tid);
            CP_COMMIT;

            // ---- G3: h2 x W3 (A-regs loaded once) ----
            {
                const char* Wp = smem + Aoff;
                uint4 AH[2][2], AL[2][2];
                #pragma unroll
                for (int rt = 0; rt < 2; rt++)
                    #pragma unroll
                    for (int kb = 0; kb < 2; kb++) {
                        uint32_t off = (uint32_t)((kb * 8 + 2 * wm4 + rt) * 512 + ln * 16);
                        AH[rt][kb] = *(const uint4*)(smem + H2F + off);
                        AL[rt][kb] = *(const uint4*)(smem + H2F + 8192 + off);
                    }
                #pragma unroll
                for (int kb = 0; kb < 2; kb++)
                    #pragma unroll
                    for (int nt = 0; nt < 8; nt++) {
                        int gnt = 8 * nq + nt;
                        uint2 b = *(const uint2*)(Wp + ((kb * 32 + gnt) * 32 + ln) * 8);
                        MMA16(xacc[0][nt], AH[0][kb], b.x, b.y);
                        MMA16(xacc[1][nt], AH[1][kb], b.x, b.y);
                        MMA16(xacc[0][nt], AL[0][kb], b.x, b.y);
                        MMA16(xacc[1][nt], AL[1][kb], b.x, b.y);
                    }
                if (e == 0) {   // weighted-b3 via K=8 fp16 MMA (experts as K)
                    const unsigned char* gb3 = g_w + B3OFF + (size_t)l * 4096;
                    #pragma unroll
                    for (int rt = 0; rt < 2; rt++) {
                        int r0 = 32 * wm4 + 16 * rt + g;
                        uint32_t a0 = h2pk(wsoft[r0 * 8 + 2 * tig], wsoft[r0 * 8 + 2 * tig + 1]);
                        uint32_t a1 = h2pk(wsoft[(r0 + 8) * 8 + 2 * tig], wsoft[(r0 + 8) * 8 + 2 * tig + 1]);
                        #pragma unroll
                        for (int nt = 0; nt < 8; nt++) {
                            uint32_t b = *(const uint32_t*)(gb3 + ((8 * nq + nt) * 32 + ln) * 4);
                            MMA8(xacc[rt][nt], a0, a1, b);
                        }
                    }
                }
            }
            __syncthreads();           // W3(A)/H2F readers done
            uint32_t t2 = Aoff; Aoff = Boff; Boff = t2;
        } // experts

        // ---- layer end: xacc -> XFRAG or out ----
        if (l == NL - 1) {
            #pragma unroll
            for (int rt = 0; rt < 2; rt++) {
                int r0 = 32 * wm4 + rt * 16 + g;
                #pragma unroll
                for (int nt = 0; nt < 8; nt++) {
                    int col = 64 * nq + nt * 8 + tig * 2;
                    float* cc = xacc[rt][nt];
                    *(float2*)(out + (size_t)(rowbase + r0) * ND + col) = make_float2(cc[0], cc[1]);
                    *(float2*)(out + (size_t)(rowbase + r0 + 8) * ND + col) = make_float2(cc[2], cc[3]);
                }
            }
        } else {
            #pragma unroll
            for (int rt = 0; rt < 2; rt++) {
                #pragma unroll
                for (int kb = 0; kb < 4; kb++) {
                    float* ce = xacc[rt][2 * kb];
                    float* co = xacc[rt][2 * kb + 1];
                    uint4 HI, LO;
                    split2(ce[0], ce[1], HI.x, LO.x);
                    split2(ce[2], ce[3], HI.y, LO.y);
                    split2(co[0], co[1], HI.z, LO.z);
                    split2(co[2], co[3], HI.w, LO.w);
                    uint32_t off = (uint32_t)(((4 * nq + kb) * 8 + 2 * wm4 + rt) * 512 + ln * 16);
                    *(uint4*)(smem + XFRAG + off) = HI;
                    *(uint4*)(smem + XFRAG + 65536 + off) = LO;
                }
            }
        }
    } // layers
    CP_WAIT(0);
}

extern "C" void kernel_launch(void* const* d_in, const int* in_sizes, int n_in,
                              void* d_out, int out_size)
{
    const float* src   = (const float*)d_in[0];
    const float* W1    = (const float*)d_in[1];
    const float* b1    = (const float*)d_in[2];
    const float* W2    = (const float*)d_in[3];
    const float* b2    = (const float*)d_in[4];
    const float* W3    = (const float*)d_in[5];
    const float* b3    = (const float*)d_in[6];
    const float* masks = (const float*)d_in[7];
    float* out = (float*)d_out;
    (void)in_sizes; (void)n_in; (void)out_size;

    prep_kernel<<<64, 256>>>(W1, W2, W3, b3);
    cudaFuncSetAttribute(moe_mma_kernel,
                         cudaFuncAttributeMaxDynamicSharedMemorySize, SMEM_BYTES);
    moe_mma_kernel<<<NB / TM, NTH, SMEM_BYTES>>>(src, b1, b2, masks, out);
}

// round 11
// speedup vs baseline: 2.5003x; 1.1323x over previous
#include <cuda_runtime.h>
#include <cuda_fp16.h>
#include <cstdint>
#include <math.h>

#define NL 8
#define NE 8
#define ND 256
#define NB 16384
#define TM 128
#define NTH 512

// ---------------- helpers ----------------
__device__ __forceinline__ uint32_t smem_to_u32(const void* p) {
    uint32_t a;
    asm("{ .reg .u64 t; cvta.to.shared.u64 t, %1; cvt.u32.u64 %0, t; }" : "=r"(a) : "l"(p));
    return a;
}
__device__ __forceinline__ uint32_t h2pk(float a, float b) {
    __half2 h = __floats2half2_rn(a, b);
    return *(uint32_t*)&h;
}
// exact split: a = hi + lo (both fp16), packed pairwise
__device__ __forceinline__ void split2(float a, float b, uint32_t& hi, uint32_t& lo) {
    __half ha = __float2half_rn(a), hb = __float2half_rn(b);
    __half2 hh = __halves2half2(ha, hb);
    hi = *(uint32_t*)&hh;
    lo = h2pk(a - __half2float(ha), b - __half2float(hb));
}

#define MMA16(c, A, b0, b1) \
    asm volatile("mma.sync.aligned.m16n8k16.row.col.f32.f16.f16.f32 " \
        "{%0,%1,%2,%3},{%4,%5,%6,%7},{%8,%9},{%0,%1,%2,%3};" \
        : "+f"((c)[0]), "+f"((c)[1]), "+f"((c)[2]), "+f"((c)[3]) \
        : "r"((A).x), "r"((A).y), "r"((A).z), "r"((A).w), "r"(b0), "r"(b1))

#define MMA8(c, a0, a1, b0) \
    asm volatile("mma.sync.aligned.m16n8k8.row.col.f32.f16.f16.f32 " \
        "{%0,%1,%2,%3},{%4,%5},{%6},{%0,%1,%2,%3};" \
        : "+f"((c)[0]), "+f"((c)[1]), "+f"((c)[2]), "+f"((c)[3]) \
        : "r"(a0), "r"(a1), "r"(b0))

#define CP_COMMIT asm volatile("cp.async.commit_group;" ::: "memory")
#define CP_WAIT(n) asm volatile("cp.async.wait_group %0;" :: "n"(n) : "memory")

__device__ __forceinline__ void cpya(uint32_t dst, const unsigned char* src, int bytes, int tid) {
    for (int i = tid * 16; i < bytes; i += NTH * 16)
        asm volatile("cp.async.cg.shared.global [%0], [%1], 16;" :: "r"(dst + i), "l"(src + i));
}

// ---------------- global weight images (fp16 B-fragments) ----------------
// per (l,e): W1 32768 (kb-major, halves = 16KB each) | W2 4096 | W3 16384
#define PER_LE 53248
#define B3OFF (64 * PER_LE)
__device__ __align__(16) unsigned char g_w[B3OFF + 8 * 4096];

__global__ void prep_kernel(const float* __restrict__ W1, const float* __restrict__ W2,
                            const float* __restrict__ W3, const float* __restrict__ b3) {
    const int le = blockIdx.x;
    const int t = threadIdx.x;
    unsigned char* base = g_w + (size_t)le * PER_LE;

    const float* W1p = W1 + (size_t)le * 16384;   // [64][256]
    for (int idx = t; idx < 4096; idx += 256) {   // (kb 0..15, nt 0..7, ln)
        int kb = idx >> 8, nt = (idx >> 5) & 7, ln = idx & 31;
        int g = ln >> 2, tig = ln & 3;
        int n = nt * 8 + g, k = kb * 16 + 2 * tig;
        *(uint2*)(base + idx * 8) = make_uint2(
            h2pk(W1p[n * 256 + k], W1p[n * 256 + k + 1]),
            h2pk(W1p[n * 256 + k + 8], W1p[n * 256 + k + 9]));
    }
    const float* W2p = W2 + (size_t)le * 2048;    // [32][64]
    for (int idx = t; idx < 512; idx += 256) {    // (kb 0..3, nt 0..3, ln)
        int kb = idx >> 7, nt = (idx >> 5) & 3, ln = idx & 31;
        int g = ln >> 2, tig = ln & 3;
        int n = nt * 8 + g, k = kb * 16 + 2 * tig;
        *(uint2*)(base + 32768 + idx * 8) = make_uint2(
            h2pk(W2p[n * 64 + k], W2p[n * 64 + k + 1]),
            h2pk(W2p[n * 64 + k + 8], W2p[n * 64 + k + 9]));
    }
    const float* W3p = W3 + (size_t)le * 8192;    // [256][32]
    for (int idx = t; idx < 2048; idx += 256) {   // (kb 0..1, nt 0..31, ln)
        int kb = idx >> 10, nt = (idx >> 5) & 31, ln = idx & 31;
        int g = ln >> 2, tig = ln & 3;
        int n = nt * 8 + g, k = kb * 16 + 2 * tig;
        *(uint2*)(base + 36864 + idx * 8) = make_uint2(
            h2pk(W3p[n * 32 + k], W3p[n * 32 + k + 1]),
            h2pk(W3p[n * 32 + k + 8], W3p[n * 32 + k + 9]));
    }
    if ((le & 7) == 0) {
        int l = le >> 3;
        const float* b3p = b3 + (size_t)l * 2048;  // [8][256]
        unsigned char* bb = g_w + B3OFF + (size_t)l * 4096;
        for (int idx = t; idx < 1024; idx += 256) {  // (nt 0..31, ln)
            int nt = idx >> 5, ln = idx & 31;
            int g = ln >> 2, tig = ln & 3;
            int n = nt * 8 + g;
            *(uint32_t*)(bb + idx * 4) = h2pk(b3p[2 * tig * 256 + n], b3p[(2 * tig + 1) * 256 + n]);
        }
    }
}

// ---------------- smem layout (bytes) ----------------
#define XFRAG 0          // 131072: X A-frags uint4, hi plane + lo plane @ +65536
#define BUF0  131072     // 16384
#define BUF1  147456     // 16384
#define H1F   163840     // 16384: single (hi) plane [(nq*8+rtile)*512 + ln*16]
#define H2F   180224     // 8192 : single plane
#define W2F   188416     // 4096
#define WSOFT 192512     // 4096
#define B1S   196608     // 256
#define B2S   196864     // 128
#define SMEM_BYTES 196992

__global__ void __launch_bounds__(NTH, 1)
moe_mma_kernel(const float* __restrict__ src,
               const float* __restrict__ b1, const float* __restrict__ b2,
               const float* __restrict__ masks, float* __restrict__ out)
{
    extern __shared__ char smem[];
    const uint32_t sbase = smem_to_u32(smem);
    const int tid = threadIdx.x;
    const int w = tid >> 5;
    const int ln = tid & 31;
    const int g = ln >> 2;
    const int tig = ln & 3;
    const int wm4 = w & 3;       // rowblock-pair (G1/G3)
    const int nq = w >> 2;       // n-quarter (G1/G3)
    const int rb = w >> 1;       // rowblock (G2)
    const int nhf = w & 1;       // n-half (G2)
    const int rowbase = blockIdx.x * TM;

    float* b1s = (float*)(smem + B1S);
    float* b2s = (float*)(smem + B2S);
    float* wsoft = (float*)(smem + WSOFT);

    // prologue: stage W1a(0) + W2(0) as one group (plays role of "prev G3" group)
    cpya(sbase + BUF0, g_w, 16384, tid);
    cpya(sbase + W2F, g_w + 32768, 4096, tid);
    CP_COMMIT;

    // initial X -> fp16 hi/lo A-fragment image (4 threads per row); X stays exact
    {
        const int r = tid >> 2;
        const int q4 = tid & 3;
        const float* sp = src + (size_t)(rowbase + r) * ND;
        const int rt = r >> 4;
        const int rsel = ((r & 15) >= 8) ? 1 : 0;
        #pragma unroll 4
        for (int c = 64 * q4; c < 64 * q4 + 64; c += 2) {
            int kb = c >> 4, kk = c & 15;
            int tigw = (kk & 7) >> 1;
            int reg = rsel + ((kk >= 8) ? 2 : 0);
            uint32_t hi, lo;
            split2(sp[c], sp[c + 1], hi, lo);
            uint32_t off = (uint32_t)((kb * 8 + rt) * 512 + (4 * (r & 7) + tigw) * 16 + reg * 4);
            *(uint32_t*)(smem + XFRAG + off) = hi;
            *(uint32_t*)(smem + XFRAG + 65536 + off) = lo;
        }
    }

    uint32_t Aoff = BUF0, Boff = BUF1;
    float xacc[2][8][4];

    for (int l = 0; l < NL; l++) {
        if (tid < TM) {
            const int r = tid;
            const float* mp = masks + ((size_t)l * NB + rowbase + r) * NE;
            float m[8], mx = -1e30f;
            #pragma unroll
            for (int e = 0; e < 8; e++) { m[e] = mp[e]; mx = fmaxf(mx, m[e]); }
            float s = 0.f;
            #pragma unroll
            for (int e = 0; e < 8; e++) { m[e] = expf(m[e] - mx); s += m[e]; }
            s = 1.f / s;
            #pragma unroll
            for (int e = 0; e < 8; e++) wsoft[r * 8 + e] = m[e] * s;
        }
        #pragma unroll
        for (int i = 0; i < 2; i++)
            #pragma unroll
            for (int j = 0; j < 8; j++)
                #pragma unroll
                for (int q = 0; q < 4; q++) xacc[i][j][q] = 0.f;

        for (int e = 0; e < NE; e++) {
            const int idx = l * 8 + e;
            const unsigned char* wp = g_w + (size_t)idx * PER_LE;
            const unsigned char* wn = g_w + (size_t)(idx < 63 ? idx + 1 : 63) * PER_LE;

            // C1: W1b -> B (hides under G1a)
            cpya(sbase + Boff, wp + 16384, 16384, tid);
            CP_COMMIT;
            CP_WAIT(1);                // prev-G3 group (W1a, W2) done
            __syncthreads();

            float bb1v = (tid < 64) ? b1[(size_t)idx * 64 + tid] : 0.f;
            float bb2v = (tid >= 64 && tid < 96) ? b2[(size_t)idx * 32 + tid - 64] : 0.f;

            // ---- G1a: kb 0..7 from A ----
            float c1[2][2][4];
            #pragma unroll
            for (int i = 0; i < 2; i++)
                #pragma unroll
                for (int j = 0; j < 2; j++)
                    #pragma unroll
                    for (int q = 0; q < 4; q++) c1[i][j][q] = 0.f;
            {
                const char* Ap = smem + Aoff;
                #pragma unroll
                for (int kb = 0; kb < 8; kb++) {
                    const char* xb = smem + XFRAG + (kb * 8 + 2 * wm4) * 512 + ln * 16;
                    uint4 Ah0 = *(const uint4*)xb;
                    uint4 Ah1 = *(const uint4*)(xb + 512);
                    uint4 Al0 = *(const uint4*)(xb + 65536);
                    uint4 Al1 = *(const uint4*)(xb + 65536 + 512);
                    #pragma unroll
                    for (int nt = 0; nt < 2; nt++) {
                        uint2 b = *(const uint2*)(Ap + ((kb * 8 + 2 * nq + nt) * 32 + ln) * 8);
                        MMA16(c1[0][nt], Ah0, b.x, b.y);
                        MMA16(c1[1][nt], Ah1, b.x, b.y);
                        MMA16(c1[0][nt], Al0, b.x, b.y);
                        MMA16(c1[1][nt], Al1, b.x, b.y);
                    }
                }
            }
            if (tid < 64) b1s[tid] = bb1v;
            else if (tid < 96) b2s[tid - 64] = bb2v;
            CP_WAIT(0);                // W1b landed
            __syncthreads();

            // ---- G1b: kb 8..15 from B ----
            {
                const char* Bp = smem + Boff;
                #pragma unroll
                for (int kb = 8; kb < 16; kb++) {
                    const char* xb = smem + XFRAG + (kb * 8 + 2 * wm4) * 512 + ln * 16;
                    uint4 Ah0 = *(const uint4*)xb;
                    uint4 Ah1 = *(const uint4*)(xb + 512);
                    uint4 Al0 = *(const uint4*)(xb + 65536);
                    uint4 Al1 = *(const uint4*)(xb + 65536 + 512);
                    #pragma unroll
                    for (int nt = 0; nt < 2; nt++) {
                        uint2 b = *(const uint2*)(Bp + (((kb - 8) * 8 + 2 * nq + nt) * 32 + ln) * 8);
                        MMA16(c1[0][nt], Ah0, b.x, b.y);
                        MMA16(c1[1][nt], Ah1, b.x, b.y);
                        MMA16(c1[0][nt], Al0, b.x, b.y);
                        MMA16(c1[1][nt], Al1, b.x, b.y);
                    }
                }
            }
            // C2: W3 -> A (A readers all done at prior barrier; hides under epi+G2)
            cpya(sbase + Aoff, wp + 36864, 16384, tid);
            CP_COMMIT;

            // ---- D1 epilogue: bias+relu -> single-fp16 h1 frags -> H1F ----
            {
                #pragma unroll
                for (int rt = 0; rt < 2; rt++) {
                    float v[2][4];
                    #pragma unroll
                    for (int nt = 0; nt < 2; nt++)
                        #pragma unroll
                        for (int ci = 0; ci < 4; ci++) {
                            int h = 16 * nq + 8 * nt + 2 * tig + (ci & 1);
                            v[nt][ci] = fmaxf(c1[rt][nt][ci] + b1s[h], 0.f);
                        }
                    uint4 HI;
                    HI.x = h2pk(v[0][0], v[0][1]);
                    HI.y = h2pk(v[0][2], v[0][3]);
                    HI.z = h2pk(v[1][0], v[1][1]);
                    HI.w = h2pk(v[1][2], v[1][3]);
                    uint32_t off = (uint32_t)((nq * 8 + 2 * wm4 + rt) * 512 + ln * 16);
                    *(uint4*)(smem + H1F + off) = HI;
                }
            }
            __syncthreads();           // h1 visible

            // ---- G2: h1 (H1F) x W2 ----
            float c2[2][4];
            #pragma unroll
            for (int j = 0; j < 2; j++)
                #pragma unroll
                for (int q = 0; q < 4; q++) c2[j][q] = 0.f;
            {
                #pragma unroll
                for (int kb = 0; kb < 4; kb++) {
                    uint32_t off = (uint32_t)((kb * 8 + rb) * 512 + ln * 16);
                    uint4 Ah = *(const uint4*)(smem + H1F + off);
                    #pragma unroll
                    for (int nt = 0; nt < 2; nt++) {
                        uint2 b = *(const uint2*)(smem + W2F + ((kb * 4 + 2 * nhf + nt) * 32 + ln) * 8);
                        MMA16(c2[nt], Ah, b.x, b.y);
                    }
                }
            }
            // ---- D2 epilogue: bias+relu, *softmax -> single-fp16 h2 -> H2F ----
            {
                float wg0 = wsoft[(16 * rb + g) * 8 + e];
                float wg1 = wsoft[(16 * rb + 8 + g) * 8 + e];
                float v[2][4];
                #pragma unroll
                for (int nt = 0; nt < 2; nt++)
                    #pragma unroll
                    for (int ci = 0; ci < 4; ci++) {
                        int h = 16 * nhf + 8 * nt + 2 * tig + (ci & 1);
                        v[nt][ci] = fmaxf(c2[nt][ci] + b2s[h], 0.f) * ((ci < 2) ? wg0 : wg1);
                    }
                uint4 HI;
                HI.x = h2pk(v[0][0], v[0][1]);
                HI.y = h2pk(v[0][2], v[0][3]);
                HI.z = h2pk(v[1][0], v[1][1]);
                HI.w = h2pk(v[1][2], v[1][3]);
                uint32_t off = (uint32_t)((nhf * 8 + rb) * 512 + ln * 16);
                *(uint4*)(smem + H2F + off) = HI;
            }
            CP_WAIT(0);                // W3 (A) landed
            __syncthreads();           // h2 + W3 visible; H1F, W2F dead
            // C3: next W1a -> B, next W2 -> W2F (hides under G3; waited next expert)
            cpya(sbase + Boff, wn, 16384, tid);
            cpya(sbase + W2F, wn + 32768, 4096, tid);
            CP_COMMIT;

            // ---- G3: h2 x W3 (A-regs loaded once) ----
            {
                const char* Wp = smem + Aoff;
                uint4 AH[2][2];
                #pragma unroll
                for (int rt = 0; rt < 2; rt++)
                    #pragma unroll
                    for (int kb = 0; kb < 2; kb++) {
                        uint32_t off = (uint32_t)((kb * 8 + 2 * wm4 + rt) * 512 + ln * 16);
                        AH[rt][kb] = *(const uint4*)(smem + H2F + off);
                    }
                #pragma unroll
                for (int kb = 0; kb < 2; kb++)
                    #pragma unroll
                    for (int nt = 0; nt < 8; nt++) {
                        int gnt = 8 * nq + nt;
                        uint2 b = *(const uint2*)(Wp + ((kb * 32 + gnt) * 32 + ln) * 8);
                        MMA16(xacc[0][nt], AH[0][kb], b.x, b.y);
                        MMA16(xacc[1][nt], AH[1][kb], b.x, b.y);
                    }
                if (e == 0) {   // weighted-b3 via K=8 fp16 MMA (experts as K)
                    const unsigned char* gb3 = g_w + B3OFF + (size_t)l * 4096;
                    #pragma unroll
                    for (int rt = 0; rt < 2; rt++) {
                        int r0 = 32 * wm4 + 16 * rt + g;
                        uint32_t a0 = h2pk(wsoft[r0 * 8 + 2 * tig], wsoft[r0 * 8 + 2 * tig + 1]);
                        uint32_t a1 = h2pk(wsoft[(r0 + 8) * 8 + 2 * tig], wsoft[(r0 + 8) * 8 + 2 * tig + 1]);
                        #pragma unroll
                        for (int nt = 0; nt < 8; nt++) {
                            uint32_t b = *(const uint32_t*)(gb3 + ((8 * nq + nt) * 32 + ln) * 4);
                            MMA8(xacc[rt][nt], a0, a1, b);
                        }
                    }
                }
            }
            __syncthreads();           // W3(A)/H2F readers done
            uint32_t t2 = Aoff; Aoff = Boff; Boff = t2;
        } // experts

        // ---- layer end: xacc -> XFRAG (exact hi/lo) or out ----
        if (l == NL - 1) {
            #pragma unroll
            for (int rt = 0; rt < 2; rt++) {
                int r0 = 32 * wm4 + rt * 16 + g;
                #pragma unroll
                for (int nt = 0; nt < 8; nt++) {
                    int col = 64 * nq + nt * 8 + tig * 2;
                    float* cc = xacc[rt][nt];
                    *(float2*)(out + (size_t)(rowbase + r0) * ND + col) = make_float2(cc[0], cc[1]);
                    *(float2*)(out + (size_t)(rowbase + r0 + 8) * ND + col) = make_float2(cc[2], cc[3]);
                }
            }
        } else {
            #pragma unroll
            for (int rt = 0; rt < 2; rt++) {
                #pragma unroll
                for (int kb = 0; kb < 4; kb++) {
                    float* ce = xacc[rt][2 * kb];
                    float* co = xacc[rt][2 * kb + 1];
                    uint4 HI, LO;
                    split2(ce[0], ce[1], HI.x, LO.x);
                    split2(ce[2], ce[3], HI.y, LO.y);
                    split2(co[0], co[1], HI.z, LO.z);
                    split2(co[2], co[3], HI.w, LO.w);
                    uint32_t off = (uint32_t)(((4 * nq + kb) * 8 + 2 * wm4 + rt) * 512 + ln * 16);
                    *(uint4*)(smem + XFRAG + off) = HI;
                    *(uint4*)(smem + XFRAG + 65536 + off) = LO;
                }
            }
        }
    } // layers
    CP_WAIT(0);
}

extern "C" void kernel_launch(void* const* d_in, const int* in_sizes, int n_in,
                              void* d_out, int out_size)
{
    const float* src   = (const float*)d_in[0];
    const float* W1    = (const float*)d_in[1];
    const float* b1    = (const float*)d_in[2];
    const float* W2    = (const float*)d_in[3];
    const float* b2    = (const float*)d_in[4];
    const float* W3    = (const float*)d_in[5];
    const float* b3    = (const float*)d_in[6];
    const float* masks = (const float*)d_in[7];
    float* out = (float*)d_out;
    (void)in_sizes; (void)n_in; (void)out_size;

    prep_kernel<<<64, 256>>>(W1, W2, W3, b3);
    cudaFuncSetAttribute(moe_mma_kernel,
                         cudaFuncAttributeMaxDynamicSharedMemorySize, SMEM_BYTES);
    moe_mma_kernel<<<NB / TM, NTH, SMEM_BYTES>>>(src, b1, b2, masks, out);
}

// round 12
// speedup vs baseline: 2.5945x; 1.0377x over previous
#include <cuda_runtime.h>
#include <cuda_fp16.h>
#include <cstdint>
#include <math.h>

#define NL 8
#define NE 8
#define ND 256
#define NB 16384
#define TM 64
#define NTH 256

// ---------------- helpers ----------------
__device__ __forceinline__ uint32_t smem_to_u32(const void* p) {
    uint32_t a;
    asm("{ .reg .u64 t; cvta.to.shared.u64 t, %1; cvt.u32.u64 %0, t; }" : "=r"(a) : "l"(p));
    return a;
}
__device__ __forceinline__ uint32_t h2pk(float a, float b) {
    __half2 h = __floats2half2_rn(a, b);
    return *(uint32_t*)&h;
}
// exact split: a = hi + lo (both fp16), packed pairwise
__device__ __forceinline__ void split2(float a, float b, uint32_t& hi, uint32_t& lo) {
    __half ha = __float2half_rn(a), hb = __float2half_rn(b);
    __half2 hh = __halves2half2(ha, hb);
    hi = *(uint32_t*)&hh;
    lo = h2pk(a - __half2float(ha), b - __half2float(hb));
}

#define MMA16(c, A, b0, b1) \
    asm volatile("mma.sync.aligned.m16n8k16.row.col.f32.f16.f16.f32 " \
        "{%0,%1,%2,%3},{%4,%5,%6,%7},{%8,%9},{%0,%1,%2,%3};" \
        : "+f"((c)[0]), "+f"((c)[1]), "+f"((c)[2]), "+f"((c)[3]) \
        : "r"((A).x), "r"((A).y), "r"((A).z), "r"((A).w), "r"(b0), "r"(b1))

#define MMA8(c, a0, a1, b0) \
    asm volatile("mma.sync.aligned.m16n8k8.row.col.f32.f16.f16.f32 " \
        "{%0,%1,%2,%3},{%4,%5},{%6},{%0,%1,%2,%3};" \
        : "+f"((c)[0]), "+f"((c)[1]), "+f"((c)[2]), "+f"((c)[3]) \
        : "r"(a0), "r"(a1), "r"(b0))

#define CP_COMMIT asm volatile("cp.async.commit_group;" ::: "memory")
#define CP_WAIT(n) asm volatile("cp.async.wait_group %0;" :: "n"(n) : "memory")

__device__ __forceinline__ void cpya(uint32_t dst, const unsigned char* src, int bytes, int tid) {
    for (int i = tid * 16; i < bytes; i += NTH * 16)
        asm volatile("cp.async.cg.shared.global [%0], [%1], 16;" :: "r"(dst + i), "l"(src + i));
}

// ---------------- global weight images (fp16 B-fragments) ----------------
// per (l,e): W1 32768 (kb-major, halves = 16KB each) | W2 4096 | W3 16384
#define PER_LE 53248
#define B3OFF (64 * PER_LE)
__device__ __align__(16) unsigned char g_w[B3OFF + 8 * 4096];

__global__ void prep_kernel(const float* __restrict__ W1, const float* __restrict__ W2,
                            const float* __restrict__ W3, const float* __restrict__ b3) {
    const int le = blockIdx.x;
    const int t = threadIdx.x;
    unsigned char* base = g_w + (size_t)le * PER_LE;

    const float* W1p = W1 + (size_t)le * 16384;   // [64][256]
    for (int idx = t; idx < 4096; idx += 256) {   // (kb 0..15, nt 0..7, ln)
        int kb = idx >> 8, nt = (idx >> 5) & 7, ln = idx & 31;
        int g = ln >> 2, tig = ln & 3;
        int n = nt * 8 + g, k = kb * 16 + 2 * tig;
        *(uint2*)(base + idx * 8) = make_uint2(
            h2pk(W1p[n * 256 + k], W1p[n * 256 + k + 1]),
            h2pk(W1p[n * 256 + k + 8], W1p[n * 256 + k + 9]));
    }
    const float* W2p = W2 + (size_t)le * 2048;    // [32][64]
    for (int idx = t; idx < 512; idx += 256) {    // (kb 0..3, nt 0..3, ln)
        int kb = idx >> 7, nt = (idx >> 5) & 3, ln = idx & 31;
        int g = ln >> 2, tig = ln & 3;
        int n = nt * 8 + g, k = kb * 16 + 2 * tig;
        *(uint2*)(base + 32768 + idx * 8) = make_uint2(
            h2pk(W2p[n * 64 + k], W2p[n * 64 + k + 1]),
            h2pk(W2p[n * 64 + k + 8], W2p[n * 64 + k + 9]));
    }
    const float* W3p = W3 + (size_t)le * 8192;    // [256][32]
    for (int idx = t; idx < 2048; idx += 256) {   // (kb 0..1, nt 0..31, ln)
        int kb = idx >> 10, nt = (idx >> 5) & 31, ln = idx & 31;
        int g = ln >> 2, tig = ln & 3;
        int n = nt * 8 + g, k = kb * 16 + 2 * tig;
        *(uint2*)(base + 36864 + idx * 8) = make_uint2(
            h2pk(W3p[n * 32 + k], W3p[n * 32 + k + 1]),
            h2pk(W3p[n * 32 + k + 8], W3p[n * 32 + k + 9]));
    }
    if ((le & 7) == 0) {
        int l = le >> 3;
        const float* b3p = b3 + (size_t)l * 2048;  // [8][256]
        unsigned char* bb = g_w + B3OFF + (size_t)l * 4096;
        for (int idx = t; idx < 1024; idx += 256) {  // (nt 0..31, ln)
            int nt = idx >> 5, ln = idx & 31;
            int g = ln >> 2, tig = ln & 3;
            int n = nt * 8 + g;
            *(uint32_t*)(bb + idx * 4) = h2pk(b3p[2 * tig * 256 + n], b3p[(2 * tig + 1) * 256 + n]);
        }
    }
}

// ---------------- smem layout (bytes), TM=64, 2 CTAs/SM ----------------
#define XFRAG 0          // 65536: X A-frags uint4 [(kb*4+rt)*512 + ln*16], lo @ +32768
#define BUF0  65536      // 16384
#define BUF1  81920      // 16384 (h1 overlays current Q's first 8192)
#define H2F   98304      // 4096 : single plane
#define W2F   102400     // 4096
#define WSOFT 106496     // 2048 (64 x 8 f32)
#define B1S   108544     // 256
#define B2S   108800     // 128
#define SMEM_BYTES 108928
#define XLO 32768

__global__ void __launch_bounds__(NTH, 2)
moe_mma_kernel(const float* __restrict__ src,
               const float* __restrict__ b1, const float* __restrict__ b2,
               const float* __restrict__ masks, float* __restrict__ out)
{
    extern __shared__ char smem[];
    const uint32_t sbase = smem_to_u32(smem);
    const int tid = threadIdx.x;
    const int w = tid >> 5;
    const int ln = tid & 31;
    const int g = ln >> 2;
    const int tig = ln & 3;
    const int rp  = w & 1;       // rowtile-pair (G1/G3): rt = 2*rp + rtl
    const int nq1 = w >> 1;      // n-quarter 0..3 (G1: nt pair; G3: 8-nt group)
    const int rb  = w & 3;       // rowblock (G2)
    const int nh2 = w >> 2;      // n-half (G2)
    const int rowbase = blockIdx.x * TM;

    float* b1s = (float*)(smem + B1S);
    float* b2s = (float*)(smem + B2S);
    float* wsoft = (float*)(smem + WSOFT);

    // prologue: stage W1a(0) + W2(0) as one group (plays role of "prev C3" group)
    cpya(sbase + BUF0, g_w, 16384, tid);
    cpya(sbase + W2F, g_w + 32768, 4096, tid);
    CP_COMMIT;

    // initial X -> fp16 hi/lo A-fragment image (4 threads per row); X stays exact
    {
        const int r = tid >> 2;
        const int q4 = tid & 3;
        const float* sp = src + (size_t)(rowbase + r) * ND;
        const int rt = r >> 4;
        const int rsel = ((r & 15) >= 8) ? 1 : 0;
        #pragma unroll 4
        for (int c = 64 * q4; c < 64 * q4 + 64; c += 2) {
            int kb = c >> 4, kk = c & 15;
            int tigw = (kk & 7) >> 1;
            int reg = rsel + ((kk >= 8) ? 2 : 0);
            uint32_t hi, lo;
            split2(sp[c], sp[c + 1], hi, lo);
            uint32_t off = (uint32_t)((kb * 4 + rt) * 512 + (4 * (r & 7) + tigw) * 16 + reg * 4);
            *(uint32_t*)(smem + XFRAG + off) = hi;
            *(uint32_t*)(smem + XFRAG + XLO + off) = lo;
        }
    }

    uint32_t Aoff = BUF0, Boff = BUF1;
    float xacc[2][8][4];

    for (int l = 0; l < NL; l++) {
        if (tid < TM) {
            const int r = tid;
            const float* mp = masks + ((size_t)l * NB + rowbase + r) * NE;
            float m[8], mx = -1e30f;
            #pragma unroll
            for (int e = 0; e < 8; e++) { m[e] = mp[e]; mx = fmaxf(mx, m[e]); }
            float s = 0.f;
            #pragma unroll
            for (int e = 0; e < 8; e++) { m[e] = expf(m[e] - mx); s += m[e]; }
            s = 1.f / s;
            #pragma unroll
            for (int e = 0; e < 8; e++) wsoft[r * 8 + e] = m[e] * s;
        }
        #pragma unroll
        for (int i = 0; i < 2; i++)
            #pragma unroll
            for (int j = 0; j < 8; j++)
                #pragma unroll
                for (int q = 0; q < 4; q++) xacc[i][j][q] = 0.f;

        for (int e = 0; e < NE; e++) {
            const int idx = l * 8 + e;
            const unsigned char* wp = g_w + (size_t)idx * PER_LE;
            const unsigned char* wn = g_w + (size_t)(idx < 63 ? idx + 1 : 63) * PER_LE;

            // C1: W1b -> B (hides under G1a)
            cpya(sbase + Boff, wp + 16384, 16384, tid);
            CP_COMMIT;
            CP_WAIT(1);                // prev-C3 group (W1a, W2) done
            __syncthreads();           // X/wsoft also visible

            float bb1v = (tid < 64) ? b1[(size_t)idx * 64 + tid] : 0.f;
            float bb2v = (tid >= 64 && tid < 96) ? b2[(size_t)idx * 32 + tid - 64] : 0.f;

            // ---- G1a: kb 0..7 from A ----
            float c1[2][2][4];
            #pragma unroll
            for (int i = 0; i < 2; i++)
                #pragma unroll
                for (int j = 0; j < 2; j++)
                    #pragma unroll
                    for (int q = 0; q < 4; q++) c1[i][j][q] = 0.f;
            {
                const char* Ap = smem + Aoff;
                #pragma unroll
                for (int kb = 0; kb < 8; kb++) {
                    const char* xb = smem + XFRAG + (kb * 4 + 2 * rp) * 512 + ln * 16;
                    uint4 Ah0 = *(const uint4*)xb;
                    uint4 Ah1 = *(const uint4*)(xb + 512);
                    uint4 Al0 = *(const uint4*)(xb + XLO);
                    uint4 Al1 = *(const uint4*)(xb + XLO + 512);
                    #pragma unroll
                    for (int nt = 0; nt < 2; nt++) {
                        uint2 b = *(const uint2*)(Ap + ((kb * 8 + 2 * nq1 + nt) * 32 + ln) * 8);
                        MMA16(c1[0][nt], Ah0, b.x, b.y);
                        MMA16(c1[1][nt], Ah1, b.x, b.y);
                        MMA16(c1[0][nt], Al0, b.x, b.y);
                        MMA16(c1[1][nt], Al1, b.x, b.y);
                    }
                }
            }
            if (tid < 64) b1s[tid] = bb1v;
            else if (tid < 96) b2s[tid - 64] = bb2v;
            CP_WAIT(0);                // W1b landed
            __syncthreads();           // A readers done (W3 may target A)

            // ---- G1b: kb 8..15 from B ----
            {
                const char* Bp = smem + Boff;
                #pragma unroll
                for (int kb = 8; kb < 16; kb++) {
                    const char* xb = smem + XFRAG + (kb * 4 + 2 * rp) * 512 + ln * 16;
                    uint4 Ah0 = *(const uint4*)xb;
                    uint4 Ah1 = *(const uint4*)(xb + 512);
                    uint4 Al0 = *(const uint4*)(xb + XLO);
                    uint4 Al1 = *(const uint4*)(xb + XLO + 512);
                    #pragma unroll
                    for (int nt = 0; nt < 2; nt++) {
                        uint2 b = *(const uint2*)(Bp + (((kb - 8) * 8 + 2 * nq1 + nt) * 32 + ln) * 8);
                        MMA16(c1[0][nt], Ah0, b.x, b.y);
                        MMA16(c1[1][nt], Ah1, b.x, b.y);
                        MMA16(c1[0][nt], Al0, b.x, b.y);
                        MMA16(c1[1][nt], Al1, b.x, b.y);
                    }
                }
            }
            // C2: W3 -> A (A free since post-G1a sync; hides under epi+G2)
            cpya(sbase + Aoff, wp + 36864, 16384, tid);
            CP_COMMIT;
            __syncthreads();           // all B(W1b) readers done -> h1 may overlay B

            // ---- D1 epilogue: bias+relu -> single-fp16 h1 frags overlaid in B ----
            {
                char* Qp = smem + Boff;
                #pragma unroll
                for (int rt = 0; rt < 2; rt++) {
                    float v[2][4];
                    #pragma unroll
                    for (int nt = 0; nt < 2; nt++)
                        #pragma unroll
                        for (int ci = 0; ci < 4; ci++) {
                            int h = 16 * nq1 + 8 * nt + 2 * tig + (ci & 1);
                            v[nt][ci] = fmaxf(c1[rt][nt][ci] + b1s[h], 0.f);
                        }
                    uint4 HI;
                    HI.x = h2pk(v[0][0], v[0][1]);
                    HI.y = h2pk(v[0][2], v[0][3]);
                    HI.z = h2pk(v[1][0], v[1][1]);
                    HI.w = h2pk(v[1][2], v[1][3]);
                    uint32_t off = (uint32_t)((nq1 * 4 + 2 * rp + rt) * 512 + ln * 16);
                    *(uint4*)(Qp + off) = HI;
                }
            }
            __syncthreads();           // h1 visible

            // ---- G2: h1 (B overlay) x W2 ----
            float c2[2][4];
            #pragma unroll
            for (int j = 0; j < 2; j++)
                #pragma unroll
                for (int q = 0; q < 4; q++) c2[j][q] = 0.f;
            {
                const char* Qp = smem + Boff;
                #pragma unroll
                for (int kb = 0; kb < 4; kb++) {
                    uint4 Ah = *(const uint4*)(Qp + (kb * 4 + rb) * 512 + ln * 16);
                    #pragma unroll
                    for (int nt = 0; nt < 2; nt++) {
                        uint2 b = *(const uint2*)(smem + W2F + ((kb * 4 + 2 * nh2 + nt) * 32 + ln) * 8);
                        MMA16(c2[nt], Ah, b.x, b.y);
                    }
                }
            }
            // ---- D2 epilogue: bias+relu, *softmax -> single-fp16 h2 -> H2F ----
            {
                float wg0 = wsoft[(16 * rb + g) * 8 + e];
                float wg1 = wsoft[(16 * rb + 8 + g) * 8 + e];
                float v[2][4];
                #pragma unroll
                for (int nt = 0; nt < 2; nt++)
                    #pragma unroll
                    for (int ci = 0; ci < 4; ci++) {
                        int h = 16 * nh2 + 8 * nt + 2 * tig + (ci & 1);
                        v[nt][ci] = fmaxf(c2[nt][ci] + b2s[h], 0.f) * ((ci < 2) ? wg0 : wg1);
                    }
                uint4 HI;
                HI.x = h2pk(v[0][0], v[0][1]);
                HI.y = h2pk(v[0][2], v[0][3]);
                HI.z = h2pk(v[1][0], v[1][1]);
                HI.w = h2pk(v[1][2], v[1][3]);
                uint32_t off = (uint32_t)((nh2 * 4 + rb) * 512 + ln * 16);
                *(uint4*)(smem + H2F + off) = HI;
            }
            CP_WAIT(0);                // W3 (A) landed
            __syncthreads();           // h2 + W3 visible; h1(B), W2F dead
            // C3: next W1a -> B, next W2 -> W2F (hides under G3)
            cpya(sbase + Boff, wn, 16384, tid);
            cpya(sbase + W2F, wn + 32768, 4096, tid);
            CP_COMMIT;

            // ---- G3: h2 x W3 (A-regs loaded once) ----
            {
                const char* Wp = smem + Aoff;
                uint4 AH[2][2];
                #pragma unroll
                for (int rt = 0; rt < 2; rt++)
                    #pragma unroll
                    for (int kb = 0; kb < 2; kb++)
                        AH[rt][kb] = *(const uint4*)(smem + H2F + (kb * 4 + 2 * rp + rt) * 512 + ln * 16);
                #pragma unroll
                for (int kb = 0; kb < 2; kb++)
                    #pragma unroll
                    for (int nt = 0; nt < 8; nt++) {
                        int gnt = 8 * nq1 + nt;
                        uint2 b = *(const uint2*)(Wp + ((kb * 32 + gnt) * 32 + ln) * 8);
                        MMA16(xacc[0][nt], AH[0][kb], b.x, b.y);
                        MMA16(xacc[1][nt], AH[1][kb], b.x, b.y);
                    }
                if (e == 0) {   // weighted-b3 via K=8 fp16 MMA (experts as K)
                    const unsigned char* gb3 = g_w + B3OFF + (size_t)l * 4096;
                    #pragma unroll
                    for (int rt = 0; rt < 2; rt++) {
                        int r0 = 32 * rp + 16 * rt + g;
                        uint32_t a0 = h2pk(wsoft[r0 * 8 + 2 * tig], wsoft[r0 * 8 + 2 * tig + 1]);
                        uint32_t a1 = h2pk(wsoft[(r0 + 8) * 8 + 2 * tig], wsoft[(r0 + 8) * 8 + 2 * tig + 1]);
                        #pragma unroll
                        for (int nt = 0; nt < 8; nt++) {
                            uint32_t b = *(const uint32_t*)(gb3 + ((8 * nq1 + nt) * 32 + ln) * 4);
                            MMA8(xacc[rt][nt], a0, a1, b);
                        }
                    }
                }
            }
            __syncthreads();           // W3(A)/H2F readers done (next C1 targets A after swap)
            uint32_t t2 = Aoff; Aoff = Boff; Boff = t2;
        } // experts

        // ---- layer end: xacc -> XFRAG (exact hi/lo) or out ----
        if (l == NL - 1) {
            #pragma unroll
            for (int rt = 0; rt < 2; rt++) {
                int r0 = 32 * rp + rt * 16 + g;
                #pragma unroll
                for (int nt = 0; nt < 8; nt++) {
                    int col = 64 * nq1 + nt * 8 + tig * 2;
                    float* cc = xacc[rt][nt];
                    *(float2*)(out + (size_t)(rowbase + r0) * ND + col) = make_float2(cc[0], cc[1]);
                    *(float2*)(out + (size_t)(rowbase + r0 + 8) * ND + col) = make_float2(cc[2], cc[3]);
                }
            }
        } else {
            #pragma unroll
            for (int rt = 0; rt < 2; rt++) {
                #pragma unroll
                for (int kbl = 0; kbl < 4; kbl++) {
                    float* ce = xacc[rt][2 * kbl];
                    float* co = xacc[rt][2 * kbl + 1];
                    uint4 HI, LO;
                    split2(ce[0], ce[1], HI.x, LO.x);
                    split2(ce[2], ce[3], HI.y, LO.y);
                    split2(co[0], co[1], HI.z, LO.z);
                    split2(co[2], co[3], HI.w, LO.w);
                    uint32_t off = (uint32_t)(((4 * nq1 + kbl) * 4 + 2 * rp + rt) * 512 + ln * 16);
                    *(uint4*)(smem + XFRAG + off) = HI;
                    *(uint4*)(smem + XFRAG + XLO + off) = LO;
                }
            }
        }
    } // layers
    CP_WAIT(0);
}

extern "C" void kernel_launch(void* const* d_in, const int* in_sizes, int n_in,
                              void* d_out, int out_size)
{
    const float* src   = (const float*)d_in[0];
    const float* W1    = (const float*)d_in[1];
    const float* b1    = (const float*)d_in[2];
    const float* W2    = (const float*)d_in[3];
    const float* b2    = (const float*)d_in[4];
    const float* W3    = (const float*)d_in[5];
    const float* b3    = (const float*)d_in[6];
    const float* masks = (const float*)d_in[7];
    float* out = (float*)d_out;
    (void)in_sizes; (void)n_in; (void)out_size;

    prep_kernel<<<64, 256>>>(W1, W2, W3, b3);
    cudaFuncSetAttribute(moe_mma_kernel,
                         cudaFuncAttributeMaxDynamicSharedMemorySize, SMEM_BYTES);
    moe_mma_kernel<<<NB / TM, NTH, SMEM_BYTES>>>(src, b1, b2, masks, out);
}

// round 13
// speedup vs baseline: 3.0989x; 1.1944x over previous
#include <cuda_runtime.h>
#include <cuda_fp16.h>
#include <cstdint>
#include <math.h>

#define NL 8
#define NE 8
#define ND 256
#define NB 16384
#define TM 64
#define NTH 256

// ---------------- helpers ----------------
__device__ __forceinline__ uint32_t h2pk(float a, float b) {
    __half2 h = __floats2half2_rn(a, b);
    return *(uint32_t*)&h;
}
// exact split: a = hi + lo (both fp16), packed pairwise
__device__ __forceinline__ void split2(float a, float b, uint32_t& hi, uint32_t& lo) {
    __half ha = __float2half_rn(a), hb = __float2half_rn(b);
    __half2 hh = __halves2half2(ha, hb);
    hi = *(uint32_t*)&hh;
    lo = h2pk(a - __half2float(ha), b - __half2float(hb));
}

#define MMA16(c, A, b0, b1) \
    asm volatile("mma.sync.aligned.m16n8k16.row.col.f32.f16.f16.f32 " \
        "{%0,%1,%2,%3},{%4,%5,%6,%7},{%8,%9},{%0,%1,%2,%3};" \
        : "+f"((c)[0]), "+f"((c)[1]), "+f"((c)[2]), "+f"((c)[3]) \
        : "r"((A).x), "r"((A).y), "r"((A).z), "r"((A).w), "r"(b0), "r"(b1))

#define MMA8(c, a0, a1, b0) \
    asm volatile("mma.sync.aligned.m16n8k8.row.col.f32.f16.f16.f32 " \
        "{%0,%1,%2,%3},{%4,%5},{%6},{%0,%1,%2,%3};" \
        : "+f"((c)[0]), "+f"((c)[1]), "+f"((c)[2]), "+f"((c)[3]) \
        : "r"(a0), "r"(a1), "r"(b0))

// ---------------- global weight images (fp16 B-fragments) ----------------
// per (l,e): W1 32768 (kb-major contiguous) | W2 4096 | W3 16384
#define PER_LE 53248
#define B3OFF (64 * PER_LE)
__device__ __align__(16) unsigned char g_w[B3OFF + 8 * 4096];

__global__ void prep_kernel(const float* __restrict__ W1, const float* __restrict__ W2,
                            const float* __restrict__ W3, const float* __restrict__ b3) {
    const int le = blockIdx.x;
    const int t = threadIdx.x;
    unsigned char* base = g_w + (size_t)le * PER_LE;

    const float* W1p = W1 + (size_t)le * 16384;   // [64][256]
    for (int idx = t; idx < 4096; idx += 256) {   // (kb 0..15, nt 0..7, ln)
        int kb = idx >> 8, nt = (idx >> 5) & 7, ln = idx & 31;
        int g = ln >> 2, tig = ln & 3;
        int n = nt * 8 + g, k = kb * 16 + 2 * tig;
        *(uint2*)(base + idx * 8) = make_uint2(
            h2pk(W1p[n * 256 + k], W1p[n * 256 + k + 1]),
            h2pk(W1p[n * 256 + k + 8], W1p[n * 256 + k + 9]));
    }
    const float* W2p = W2 + (size_t)le * 2048;    // [32][64]
    for (int idx = t; idx < 512; idx += 256) {    // (kb 0..3, nt 0..3, ln)
        int kb = idx >> 7, nt = (idx >> 5) & 3, ln = idx & 31;
        int g = ln >> 2, tig = ln & 3;
        int n = nt * 8 + g, k = kb * 16 + 2 * tig;
        *(uint2*)(base + 32768 + idx * 8) = make_uint2(
            h2pk(W2p[n * 64 + k], W2p[n * 64 + k + 1]),
            h2pk(W2p[n * 64 + k + 8], W2p[n * 64 + k + 9]));
    }
    const float* W3p = W3 + (size_t)le * 8192;    // [256][32]
    for (int idx = t; idx < 2048; idx += 256) {   // (kb 0..1, nt 0..31, ln)
        int kb = idx >> 10, nt = (idx >> 5) & 31, ln = idx & 31;
        int g = ln >> 2, tig = ln & 3;
        int n = nt * 8 + g, k = kb * 16 + 2 * tig;
        *(uint2*)(base + 36864 + idx * 8) = make_uint2(
            h2pk(W3p[n * 32 + k], W3p[n * 32 + k + 1]),
            h2pk(W3p[n * 32 + k + 8], W3p[n * 32 + k + 9]));
    }
    if ((le & 7) == 0) {
        int l = le >> 3;
        const float* b3p = b3 + (size_t)l * 2048;  // [8][256]
        unsigned char* bb = g_w + B3OFF + (size_t)l * 4096;
        for (int idx = t; idx < 1024; idx += 256) {  // (nt 0..31, ln)
            int nt = idx >> 5, ln = idx & 31;
            int g = ln >> 2, tig = ln & 3;
            int n = nt * 8 + g;
            *(uint32_t*)(bb + idx * 4) = h2pk(b3p[2 * tig * 256 + n], b3p[(2 * tig + 1) * 256 + n]);
        }
    }
}

// ---------------- smem layout (bytes), TM=64, 2 CTAs/SM ----------------
#define XFRAG 0          // 65536: X A-frags uint4 [(kb*4+rt)*512 + ln*16], lo @ +32768
#define XLO   32768
#define H1F   65536      // 8192 : h1 A-frags [(kb*4+rt)*512 + ln*16], kb 0..3
#define H2F   73728      // 4096 : h2 A-frags [(kb*4+rt)*512 + ln*16], kb 0..1
#define WSOFT 77824      // 2048 (64 x 8 f32)
#define B1D   79872      // 512 : double-buffered b1 [2][64]
#define B2D   80384      // 256 : double-buffered b2 [2][32]
#define SMEM_BYTES 80640

__global__ void __launch_bounds__(NTH, 2)
moe_mma_kernel(const float* __restrict__ src,
               const float* __restrict__ b1, const float* __restrict__ b2,
               const float* __restrict__ masks, float* __restrict__ out)
{
    extern __shared__ char smem[];
    const int tid = threadIdx.x;
    const int w = tid >> 5;
    const int ln = tid & 31;
    const int g = ln >> 2;
    const int tig = ln & 3;
    const int rt1 = w & 3;       // G1/G2 row tile (0..3)
    const int nh1 = w >> 2;      // G1/G2 n-half (0..1)
    const int rp  = w & 1;       // G3 rowtile-pair
    const int nq1 = w >> 1;      // G3 n-quarter 0..3
    const int rowbase = blockIdx.x * TM;

    float* wsoft = (float*)(smem + WSOFT);
    float* b1d = (float*)(smem + B1D);   // [2][64]
    float* b2d = (float*)(smem + B2D);   // [2][32]

    // initial X -> fp16 hi/lo A-fragment image (4 threads per row); X stays exact
    {
        const int r = tid >> 2;
        const int q4 = tid & 3;
        const float* sp = src + (size_t)(rowbase + r) * ND;
        const int rt = r >> 4;
        const int rsel = ((r & 15) >= 8) ? 1 : 0;
        #pragma unroll 4
        for (int c = 64 * q4; c < 64 * q4 + 64; c += 2) {
            int kb = c >> 4, kk = c & 15;
            int tigw = (kk & 7) >> 1;
            int reg = rsel + ((kk >= 8) ? 2 : 0);
            uint32_t hi, lo;
            split2(sp[c], sp[c + 1], hi, lo);
            uint32_t off = (uint32_t)((kb * 4 + rt) * 512 + (4 * (r & 7) + tigw) * 16 + reg * 4);
            *(uint32_t*)(smem + XFRAG + off) = hi;
            *(uint32_t*)(smem + XFRAG + XLO + off) = lo;
        }
    }

    float xacc[2][8][4];

    for (int l = 0; l < NL; l++) {
        // ---- layer top: softmax weights, expert-0 biases ----
        if (tid < TM) {
            const int r = tid;
            const float* mp = masks + ((size_t)l * NB + rowbase + r) * NE;
            float m[8], mx = -1e30f;
            #pragma unroll
            for (int e = 0; e < 8; e++) { m[e] = mp[e]; mx = fmaxf(mx, m[e]); }
            float s = 0.f;
            #pragma unroll
            for (int e = 0; e < 8; e++) { m[e] = expf(m[e] - mx); s += m[e]; }
            s = 1.f / s;
            #pragma unroll
            for (int e = 0; e < 8; e++) wsoft[r * 8 + e] = m[e] * s;
        }
        if (tid < 64) b1d[tid] = b1[(size_t)(l * 8) * 64 + tid];
        else if (tid < 96) b2d[tid - 64] = b2[(size_t)(l * 8) * 32 + tid - 64];
        #pragma unroll
        for (int i = 0; i < 2; i++)
            #pragma unroll
            for (int j = 0; j < 8; j++)
                #pragma unroll
                for (int q = 0; q < 4; q++) xacc[i][j][q] = 0.f;
        __syncthreads();   // wsoft, e0 biases, xfrag (prev layer) visible

        for (int e = 0; e < NE; e++) {
            const int idx = l * 8 + e;
            const unsigned char* wpe = g_w + (size_t)idx * PER_LE;

            // ---- G1: X (smem) x W1 (direct LDG), warp = (1 rt, 4 nt) ----
            float c1[4][4];
            #pragma unroll
            for (int j = 0; j < 4; j++)
                #pragma unroll
                for (int q = 0; q < 4; q++) c1[j][q] = 0.f;
            {
                const uint2* w1g = (const uint2*)wpe;
                #pragma unroll
                for (int kb = 0; kb < 16; kb++) {
                    const char* xb = smem + XFRAG + (kb * 4 + rt1) * 512 + ln * 16;
                    uint4 Ah = *(const uint4*)xb;
                    uint4 Al = *(const uint4*)(xb + XLO);
                    #pragma unroll
                    for (int ntl = 0; ntl < 4; ntl++) {
                        uint2 b = w1g[(kb * 8 + nh1 * 4 + ntl) * 32 + ln];
                        MMA16(c1[ntl], Ah, b.x, b.y);
                        MMA16(c1[ntl], Al, b.x, b.y);
                    }
                }
            }

            // ---- D1 epilogue: bias+relu -> h1 A-frags (register-local pack) ----
            {
                const float* b1c = b1d + (e & 1) * 64;
                float v[4][4];
                #pragma unroll
                for (int ntl = 0; ntl < 4; ntl++)
                    #pragma unroll
                    for (int ci = 0; ci < 4; ci++) {
                        int h = (nh1 * 4 + ntl) * 8 + 2 * tig + (ci & 1);
                        v[ntl][ci] = fmaxf(c1[ntl][ci] + b1c[h], 0.f);
                    }
                #pragma unroll
                for (int kbl = 0; kbl < 2; kbl++) {
                    uint4 HI;
                    HI.x = h2pk(v[2 * kbl][0], v[2 * kbl][1]);
                    HI.y = h2pk(v[2 * kbl][2], v[2 * kbl][3]);
                    HI.z = h2pk(v[2 * kbl + 1][0], v[2 * kbl + 1][1]);
                    HI.w = h2pk(v[2 * kbl + 1][2], v[2 * kbl + 1][3]);
                    *(uint4*)(smem + H1F + ((nh1 * 2 + kbl) * 4 + rt1) * 512 + ln * 16) = HI;
                }
            }
            __syncthreads();   // B1: h1 visible (also: prev G3's H2F readers done)

            // prefetch next expert's biases into the other slot
            if (e < 7) {
                if (tid < 64) b1d[((e + 1) & 1) * 64 + tid] = b1[(size_t)(idx + 1) * 64 + tid];
                else if (tid < 96) b2d[((e + 1) & 1) * 32 + tid - 64] = b2[(size_t)(idx + 1) * 32 + tid - 64];
            }

            // ---- G2: h1 (smem) x W2 (direct LDG), warp = (1 rt, 2 nt) ----
            float c2[2][4];
            #pragma unroll
            for (int j = 0; j < 2; j++)
                #pragma unroll
                for (int q = 0; q < 4; q++) c2[j][q] = 0.f;
            {
                const uint2* w2g = (const uint2*)(wpe + 32768);
                #pragma unroll
                for (int kb = 0; kb < 4; kb++) {
                    uint4 Ah = *(const uint4*)(smem + H1F + (kb * 4 + rt1) * 512 + ln * 16);
                    #pragma unroll
                    for (int nt = 0; nt < 2; nt++) {
                        uint2 b = w2g[(kb * 4 + 2 * nh1 + nt) * 32 + ln];
                        MMA16(c2[nt], Ah, b.x, b.y);
                    }
                }
            }
            // ---- D2 epilogue: bias+relu, *softmax -> h2 A-frags ----
            {
                const float* b2c = b2d + (e & 1) * 32;
                float wg0 = wsoft[(16 * rt1 + g) * 8 + e];
                float wg1 = wsoft[(16 * rt1 + 8 + g) * 8 + e];
                float v[2][4];
                #pragma unroll
                for (int nt = 0; nt < 2; nt++)
                    #pragma unroll
                    for (int ci = 0; ci < 4; ci++) {
                        int h = 16 * nh1 + 8 * nt + 2 * tig + (ci & 1);
                        v[nt][ci] = fmaxf(c2[nt][ci] + b2c[h], 0.f) * ((ci < 2) ? wg0 : wg1);
                    }
                uint4 HI;
                HI.x = h2pk(v[0][0], v[0][1]);
                HI.y = h2pk(v[0][2], v[0][3]);
                HI.z = h2pk(v[1][0], v[1][1]);
                HI.w = h2pk(v[1][2], v[1][3]);
                *(uint4*)(smem + H2F + (nh1 * 4 + rt1) * 512 + ln * 16) = HI;
            }
            __syncthreads();   // B2: h2 visible (also: h1 readers done)

            // ---- G3: h2 (smem) x W3 (direct LDG), warp = (2 rt, 8 nt) ----
            {
                const uint2* w3g = (const uint2*)(wpe + 36864);
                uint4 AH[2][2];
                #pragma unroll
                for (int rt = 0; rt < 2; rt++)
                    #pragma unroll
                    for (int kb = 0; kb < 2; kb++)
                        AH[rt][kb] = *(const uint4*)(smem + H2F + (kb * 4 + 2 * rp + rt) * 512 + ln * 16);
                #pragma unroll
                for (int kb = 0; kb < 2; kb++)
                    #pragma unroll
                    for (int nt = 0; nt < 8; nt++) {
                        uint2 b = w3g[(kb * 32 + 8 * nq1 + nt) * 32 + ln];
                        MMA16(xacc[0][nt], AH[0][kb], b.x, b.y);
                        MMA16(xacc[1][nt], AH[1][kb], b.x, b.y);
                    }
                if (e == 0) {   // weighted-b3 via K=8 fp16 MMA (experts as K)
                    const unsigned char* gb3 = g_w + B3OFF + (size_t)l * 4096;
                    #pragma unroll
                    for (int rt = 0; rt < 2; rt++) {
                        int r0 = 32 * rp + 16 * rt + g;
                        uint32_t a0 = h2pk(wsoft[r0 * 8 + 2 * tig], wsoft[r0 * 8 + 2 * tig + 1]);
                        uint32_t a1 = h2pk(wsoft[(r0 + 8) * 8 + 2 * tig], wsoft[(r0 + 8) * 8 + 2 * tig + 1]);
                        #pragma unroll
                        for (int nt = 0; nt < 8; nt++) {
                            uint32_t b = *(const uint32_t*)(gb3 + ((8 * nq1 + nt) * 32 + ln) * 4);
                            MMA8(xacc[rt][nt], a0, a1, b);
                        }
                    }
                }
            }
            // no barrier here: G1(e+1) touches nothing shared that G3 reads;
            // H2F rewrite (D2-epi of e+1) is fenced by B1(e+1).
        } // experts

        // ---- layer end: xacc -> XFRAG (exact hi/lo) or out ----
        if (l == NL - 1) {
            #pragma unroll
            for (int rt = 0; rt < 2; rt++) {
                int r0 = 32 * rp + rt * 16 + g;
                #pragma unroll
                for (int nt = 0; nt < 8; nt++) {
                    int col = 64 * nq1 + nt * 8 + tig * 2;
                    float* cc = xacc[rt][nt];
                    *(float2*)(out + (size_t)(rowbase + r0) * ND + col) = make_float2(cc[0], cc[1]);
                    *(float2*)(out + (size_t)(rowbase + r0 + 8) * ND + col) = make_float2(cc[2], cc[3]);
                }
            }
        } else {
            #pragma unroll
            for (int rt = 0; rt < 2; rt++) {
                #pragma unroll
                for (int kbl = 0; kbl < 4; kbl++) {
                    float* ce = xacc[rt][2 * kbl];
                    float* co = xacc[rt][2 * kbl + 1];
                    uint4 HI, LO;
                    split2(ce[0], ce[1], HI.x, LO.x);
                    split2(ce[2], ce[3], HI.y, LO.y);
                    split2(co[0], co[1], HI.z, LO.z);
                    split2(co[2], co[3], HI.w, LO.w);
                    uint32_t off = (uint32_t)(((4 * nq1 + kbl) * 4 + 2 * rp + rt) * 512 + ln * 16);
                    *(uint4*)(smem + XFRAG + off) = HI;
                    *(uint4*)(smem + XFRAG + XLO + off) = LO;
                }
            }
        }
        // next layer-top __syncthreads() fences xfrag writes vs G1 reads
    } // layers
}

extern "C" void kernel_launch(void* const* d_in, const int* in_sizes, int n_in,
                              void* d_out, int out_size)
{
    const float* src   = (const float*)d_in[0];
    const float* W1    = (const float*)d_in[1];
    const float* b1    = (const float*)d_in[2];
    const float* W2    = (const float*)d_in[3];
    const float* b2    = (const float*)d_in[4];
    const float* W3    = (const float*)d_in[5];
    const float* b3    = (const float*)d_in[6];
    const float* masks = (const float*)d_in[7];
    float* out = (float*)d_out;
    (void)in_sizes; (void)n_in; (void)out_size;

    prep_kernel<<<64, 256>>>(W1, W2, W3, b3);
    cudaFuncSetAttribute(moe_mma_kernel,
                         cudaFuncAttributeMaxDynamicSharedMemorySize, SMEM_BYTES);
    moe_mma_kernel<<<NB / TM, NTH, SMEM_BYTES>>>(src, b1, b2, masks, out);
}